// round 12
// baseline (speedup 1.0000x reference)
#include <cuda_runtime.h>

#define B_ 128
#define L_ 4096
#define H_ 64
#define V_ 64
#define HALF_ 32
#define C1 0.05f
#define LN_EPS 1e-5f
#define L_PAD (L_ + 8)
#define N0_ 1195
#define N1_ 2900          /* N0_+N1_ = 4095; N1_ even (backward unrolls by 2) */
#define NT_ 192

typedef unsigned long long ull;

// Token-indexed tables (V=64): g_hs/g_he pre-scaled by (1-ALPHA)=C1.
__device__ float g_hs[V_ * HALF_];
__device__ float g_he[V_ * HALF_];
__device__ float g_ks[V_ * HALF_];
__device__ float g_ke[V_ * HALF_];

// ---------------- packed f32x2 helpers ----------------
__device__ __forceinline__ ull fma2(ull a, ull b, ull c) {
    ull d; asm("fma.rn.f32x2 %0,%1,%2,%3;" : "=l"(d) : "l"(a), "l"(b), "l"(c)); return d;
}
__device__ __forceinline__ ull mul2(ull a, ull b) {
    ull d; asm("mul.rn.f32x2 %0,%1,%2;" : "=l"(d) : "l"(a), "l"(b)); return d;
}
__device__ __forceinline__ ull add2(ull a, ull b) {
    ull d; asm("add.rn.f32x2 %0,%1,%2;" : "=l"(d) : "l"(a), "l"(b)); return d;
}
__device__ __forceinline__ ull pack2(float x) {
    ull d; asm("mov.b64 %0,{%1,%1};" : "=l"(d) : "f"(x)); return d;
}
__device__ __forceinline__ float2 unpack2(ull v) {
    float2 r; asm("mov.b64 {%0,%1},%2;" : "=f"(r.x), "=f"(r.y) : "l"(v)); return r;
}
__device__ __forceinline__ float reduce2(ull a0, ull a1) {
    ull s = add2(a0, a1);
    float2 f = unpack2(s);
    float h = f.x + f.y;
    return h + __shfl_xor_sync(0xffffffffu, h, 1);
}

// ---------------------------------------------------------------------------
// Kernel 1: per-token precompute. grid=64 (token), block=128.
// ---------------------------------------------------------------------------
__global__ void build_tables(const float* __restrict__ embed,
                             const float* __restrict__ W1, const float* __restrict__ b1,
                             const float* __restrict__ W2, const float* __restrict__ b2,
                             const float* __restrict__ gamma, const float* __restrict__ beta,
                             const float* __restrict__ Ws, const float* __restrict__ bs,
                             const float* __restrict__ We, const float* __restrict__ be)
{
    __shared__ float s_e[H_];
    __shared__ float s_a[2 * H_];
    __shared__ float s_x[H_];
    __shared__ float s_h[H_];
    __shared__ float s_mu, s_rstd;

    int tok = blockIdx.x;
    int tid = threadIdx.x;

    if (tid < H_) s_e[tid] = embed[tok * H_ + tid];
    __syncthreads();

    {
        float acc = b1[tid];
        #pragma unroll 32
        for (int h = 0; h < H_; ++h) acc = fmaf(s_e[h], __ldg(W1 + h * 2 * H_ + tid), acc);
        s_a[tid] = fmaxf(acc, 0.0f);
    }
    __syncthreads();

    if (tid < H_) {
        float acc = b2[tid];
        #pragma unroll 32
        for (int k = 0; k < 2 * H_; ++k) acc = fmaf(s_a[k], __ldg(W2 + k * H_ + tid), acc);
        s_x[tid] = s_e[tid] + acc;
    }
    __syncthreads();

    if (tid < 32) {
        float v = s_x[tid] + s_x[tid + 32];
        #pragma unroll
        for (int m = 16; m > 0; m >>= 1) v += __shfl_xor_sync(0xffffffffu, v, m);
        const float mu = v * (1.0f / H_);
        float d0 = s_x[tid] - mu, d1 = s_x[tid + 32] - mu;
        float vv = fmaf(d0, d0, d1 * d1);
        #pragma unroll
        for (int m = 16; m > 0; m >>= 1) vv += __shfl_xor_sync(0xffffffffu, vv, m);
        if (tid == 0) {
            s_mu = mu;
            s_rstd = rsqrtf(vv * (1.0f / H_) + LN_EPS);
        }
    }
    __syncthreads();

    if (tid < H_) s_h[tid] = (s_x[tid] - s_mu) * s_rstd * gamma[tid] + beta[tid];
    __syncthreads();

    int wid = tid >> 5, lane = tid & 31;
    if (wid == 0) {
        float acc = bs[lane];
        #pragma unroll 32
        for (int j = 0; j < H_; ++j) acc = fmaf(s_h[j], __ldg(Ws + j * HALF_ + lane), acc);
        float ss = acc * acc;
        #pragma unroll
        for (int m = 16; m > 0; m >>= 1) ss += __shfl_xor_sync(0xffffffffu, ss, m);
        float n = fmaxf(sqrtf(ss), 1e-12f);
        g_hs[tok * HALF_ + lane] = C1 * acc;
        g_ks[tok * HALF_ + lane] = acc / n;
    } else if (wid == 1) {
        float acc = be[lane];
        #pragma unroll 32
        for (int j = 0; j < H_; ++j) acc = fmaf(s_h[j], __ldg(We + j * HALF_ + lane), acc);
        float ss = acc * acc;
        #pragma unroll
        for (int m = 16; m > 0; m >>= 1) ss += __shfl_xor_sync(0xffffffffu, ss, m);
        float n = fmaxf(sqrtf(ss), 1e-12f);
        g_he[tok * HALF_ + lane] = C1 * acc;
        g_ke[tok * HALF_ + lane] = acc / n;
    }
}

// full 32-float key row, broadcast to every lane (8x LDS.128)
#define LOADK32(DST, TOK) { \
    const ulonglong2* p_ = (const ulonglong2*)(kT + ((TOK) << 5)); \
    ulonglong2 t0_ = p_[0], t1_ = p_[1], t2_ = p_[2], t3_ = p_[3]; \
    ulonglong2 t4_ = p_[4], t5_ = p_[5], t6_ = p_[6], t7_ = p_[7]; \
    DST[0] = t0_.x;  DST[1] = t0_.y;  DST[2] = t1_.x;  DST[3] = t1_.y; \
    DST[4] = t2_.x;  DST[5] = t2_.y;  DST[6] = t3_.x;  DST[7] = t3_.y; \
    DST[8] = t4_.x;  DST[9] = t4_.y;  DST[10] = t5_.x; DST[11] = t5_.y; \
    DST[12] = t6_.x; DST[13] = t6_.y; DST[14] = t7_.x; DST[15] = t7_.y; }

// 16-float half-row (parity layout) for the backward pass
#define LOADKP(DST, TOK) { \
    const ulonglong2* p_ = (const ulonglong2*)(kT + ((TOK) << 5) + col0); \
    ulonglong2 x_ = p_[0], y_ = p_[1], z_ = p_[2], u_ = p_[3]; \
    DST[0] = x_.x; DST[1] = x_.y; DST[2] = y_.x; DST[3] = y_.y; \
    DST[4] = z_.x; DST[5] = z_.y; DST[6] = u_.x; DST[7] = u_.y; }

// ---------------------------------------------------------------------------
// Kernel 2: time-split delta-rule scan, lane=row (NO shuffles in scan).
// block = 192 (6 warps):
//   w0: chunk0-s (SMSP0)   w1: chunk0-e (SMSP1)
//   w2: chunk1-s (SMSP2)   w3: chunk1-e (SMSP3)
//   w4: backward-s (SMSP0) w5: backward-e (SMSP1)
// Each scan warp owns a full 32x32 matrix: lane = row, 16 f32x2 cols in regs.
// Defer-1 dot: fullred_{t+1} = M^(t).k_{t+1} issued pre-update; exact
// ps_{t+1} = fullred + d_t * G(tok_t, tok_{t+1}). Serial chain: 2 FFMAs.
// r = M_c0 . p + Q . q  with p from the backward sweep over chunk1.
// ---------------------------------------------------------------------------
__global__ __launch_bounds__(NT_, 1)
void scan_kernel(const int* __restrict__ seq,
                 const float* __restrict__ Wrp, const float* __restrict__ brp,
                 const float* __restrict__ Wout, const float* __restrict__ bout,
                 float* __restrict__ out)
{
    extern __shared__ float sm[];
    float* s_ks = sm;                          // 2048
    float* s_ke = sm + 2048;                   // 2048
    float* s_hs = sm + 4096;                   // 2048
    float* s_he = sm + 6144;                   // 2048
    float* s_Gs = sm + 8192;                   // 4096
    float* s_Ge = sm + 12288;                  // 4096
    int*   s_seq = (int*)(sm + 16384);         // L_PAD ints
    float* s_p   = sm + 16384 + L_PAD;         // 64 (p_s | p_e)
    float* s_r1  = s_p + 64;                   // 64
    float* s_r2  = s_r1 + 64;                  // 64
    float* s_tmp = s_r2 + 64;                  // 64

    const int b = blockIdx.x;
    const int tid = threadIdx.x;
    const int wid = tid >> 5;
    const int lane = tid & 31;

    // stage sequence + tables
    {
        const int* seqb = seq + b * L_;
        for (int k = tid; k < L_; k += NT_) s_seq[k] = seqb[k];
        if (tid < 8) s_seq[L_ + tid] = 0;
    }
    for (int k = tid; k < V_ * HALF_; k += NT_) {
        s_ks[k] = g_ks[k];
        s_ke[k] = g_ke[k];
        s_hs[k] = g_hs[k];
        s_he[k] = g_he[k];
    }
    __syncthreads();

    // Gram tables in-CTA (symmetric)
    for (int idx = tid; idx < V_ * V_; idx += NT_) {
        const int a = idx >> 6, c = idx & 63;
        float ss = 0.f, se = 0.f;
        #pragma unroll
        for (int j = 0; j < HALF_; ++j) {
            ss = fmaf(s_ks[a * HALF_ + j], s_ks[c * HALF_ + j], ss);
            se = fmaf(s_ke[a * HALF_ + j], s_ke[c * HALF_ + j], se);
        }
        s_Gs[idx] = ss;
        s_Ge[idx] = se;
    }
    __syncthreads();

    const float invL = 1.0f / (float)L_;

    ull m[16];
    bool my_is_e = false;

    if (wid < 4) {
        // ---------------- forward chunk scan, lane = row ----------------
        const bool is_e = (wid & 1) != 0;
        const bool c1 = (wid >= 2);
        my_is_e = is_e;
        const float* kT = is_e ? s_ke : s_ks;
        const float* hT = is_e ? s_he : s_hs;
        const float* gT = is_e ? s_Ge : s_Gs;
        const int* toks = s_seq + (c1 ? N0_ : 0);
        const int N = c1 ? N1_ : N0_;
        const float scStep = is_e ? invL : 0.0f;
        float sc = is_e ? (c1 ? (float)(N0_ + 1) * invL : invL) : 1.0f;

        ull KA[16], KB[16];
        #pragma unroll
        for (int j = 0; j < 16; ++j) m[j] = 0ull;

        int tok_cur = toks[0];
        int tok_nxt = toks[1];
        LOADK32(KA, tok_cur);

        float fullred = 0.0f, dm1 = 0.0f, g_cur = 0.0f;
        float hsc_cur = sc * hT[(tok_cur << 5) + lane];
        float csc_cur = -C1 * sc;

        #define STEPF(T, KC, KN) { \
            const int tok_n2 = toks[(T) + 2]; \
            LOADK32(KN, tok_nxt); \
            /* dot on PRE-update m with k_{t+1} (4 indep chains) */ \
            ull a0_ = mul2(m[0], KN[0]),  a1_ = mul2(m[1], KN[1]); \
            ull a2_ = mul2(m[2], KN[2]),  a3_ = mul2(m[3], KN[3]); \
            a0_ = fma2(m[4],  KN[4],  a0_); a1_ = fma2(m[5],  KN[5],  a1_); \
            a2_ = fma2(m[6],  KN[6],  a2_); a3_ = fma2(m[7],  KN[7],  a3_); \
            a0_ = fma2(m[8],  KN[8],  a0_); a1_ = fma2(m[9],  KN[9],  a1_); \
            a2_ = fma2(m[10], KN[10], a2_); a3_ = fma2(m[11], KN[11], a3_); \
            a0_ = fma2(m[12], KN[12], a0_); a1_ = fma2(m[13], KN[13], a1_); \
            a2_ = fma2(m[14], KN[14], a2_); a3_ = fma2(m[15], KN[15], a3_); \
            /* off-chain scalar prefetch */ \
            const float g_nxt = gT[(tok_cur << 6) + tok_nxt]; \
            const float h_nxt = hT[(tok_nxt << 5) + lane]; \
            sc += scStep; \
            /* serial chain: 2 FFMAs */ \
            const float ps_ = fmaf(dm1, g_cur, fullred); \
            const float dn_ = fmaf(csc_cur, ps_, hsc_cur); \
            const ull dn2_ = pack2(dn_); \
            /* rank-1 update with k_t */ \
            m[0]  = fma2(dn2_, KC[0],  m[0]);  m[1]  = fma2(dn2_, KC[1],  m[1]); \
            m[2]  = fma2(dn2_, KC[2],  m[2]);  m[3]  = fma2(dn2_, KC[3],  m[3]); \
            m[4]  = fma2(dn2_, KC[4],  m[4]);  m[5]  = fma2(dn2_, KC[5],  m[5]); \
            m[6]  = fma2(dn2_, KC[6],  m[6]);  m[7]  = fma2(dn2_, KC[7],  m[7]); \
            m[8]  = fma2(dn2_, KC[8],  m[8]);  m[9]  = fma2(dn2_, KC[9],  m[9]); \
            m[10] = fma2(dn2_, KC[10], m[10]); m[11] = fma2(dn2_, KC[11], m[11]); \
            m[12] = fma2(dn2_, KC[12], m[12]); m[13] = fma2(dn2_, KC[13], m[13]); \
            m[14] = fma2(dn2_, KC[14], m[14]); m[15] = fma2(dn2_, KC[15], m[15]); \
            /* finish reduce (pure per-lane ALU tree, no shfl) */ \
            { ull s01_ = add2(a0_, a1_); \
              ull s23_ = add2(a2_, a3_); \
              float2 f_ = unpack2(add2(s01_, s23_)); \
              fullred = f_.x + f_.y; } \
            dm1 = dn_; g_cur = g_nxt; \
            hsc_cur = sc * h_nxt; csc_cur = -C1 * sc; \
            tok_cur = tok_nxt; tok_nxt = tok_n2; }

        int t = 0;
        #pragma unroll 1
        for (; t + 1 < N; t += 2) {
            STEPF(t,     KA, KB);
            STEPF(t + 1, KB, KA);
        }
        if (t < N) { STEPF(t, KA, KB); }
        #undef STEPF

        // readout: M^(N) . k_{toks[N]}
        const float r_out = fmaf(dm1, g_cur, fullred);
        if (c1) s_r2[(is_e ? HALF_ : 0) + lane] = r_out;   // Q . q
        // chunk0 keeps m for the epilogue
    } else {
        // ---------------- backward vector pass over chunk1 --------------
        // p = (A_{N0} ... A_{L-2}) q,  A_t = I - c_t k_t k_t^T
        const bool is_e = (wid == 5);
        my_is_e = is_e;
        const float* kT = is_e ? s_ke : s_ks;
        const float* gT = is_e ? s_Ge : s_Gs;
        const int col0 = (lane & 1) << 4;
        const float cBase = is_e ? C1 * (float)(L_ - 1) * invL : C1;
        const float cStep = is_e ? -C1 * invL : 0.0f;

        ull u[8], ka[8], kb[8];
        const int tokq = s_seq[L_ - 1];
        LOADKP(u, tokq);                      // u = q

        int tok_c = s_seq[L_ - 2];
        int tok_p = tok_c;
        LOADKP(ka, tok_c);

        float raw;
        {
            ull a0 = mul2(ka[0], u[0]), a1 = mul2(ka[1], u[1]);
            a0 = fma2(ka[2], u[2], a0); a1 = fma2(ka[3], u[3], a1);
            a0 = fma2(ka[4], u[4], a0); a1 = fma2(ka[5], u[5], a1);
            a0 = fma2(ka[6], u[6], a0); a1 = fma2(ka[7], u[7], a1);
            raw = reduce2(a0, a1);            // k_0 . u (exact)
        }
        float dprev = 0.0f;
        float c = cBase;

        #define BITER(KC, KN, J) { \
            const int tok_n = s_seq[L_ - 3 - (J)]; \
            LOADKP(KN, tok_n); \
            ull a0_ = mul2(KN[0], u[0]), a1_ = mul2(KN[1], u[1]); \
            a0_ = fma2(KN[2], u[2], a0_); a1_ = fma2(KN[3], u[3], a1_); \
            a0_ = fma2(KN[4], u[4], a0_); a1_ = fma2(KN[5], u[5], a1_); \
            a0_ = fma2(KN[6], u[6], a0_); a1_ = fma2(KN[7], u[7], a1_); \
            const float g_ = gT[(tok_c << 6) + tok_p]; \
            const float d_ = fmaf(-dprev, c * g_, c * raw); \
            const ull nd2_ = pack2(-d_); \
            u[0] = fma2(nd2_, KC[0], u[0]); u[1] = fma2(nd2_, KC[1], u[1]); \
            u[2] = fma2(nd2_, KC[2], u[2]); u[3] = fma2(nd2_, KC[3], u[3]); \
            u[4] = fma2(nd2_, KC[4], u[4]); u[5] = fma2(nd2_, KC[5], u[5]); \
            u[6] = fma2(nd2_, KC[6], u[6]); u[7] = fma2(nd2_, KC[7], u[7]); \
            raw = reduce2(a0_, a1_); \
            dprev = d_; tok_p = tok_c; tok_c = tok_n; c += cStep; }

        #pragma unroll 1
        for (int j = 0; j < N1_; j += 2) {
            BITER(ka, kb, j);
            BITER(kb, ka, j + 1);
        }
        #undef BITER

        if (lane < 2) {
            ull* po = (ull*)(s_p + (is_e ? HALF_ : 0) + col0);
            #pragma unroll
            for (int i = 0; i < 8; ++i) po[i] = u[i];
        }
    }
    __syncthreads();

    // r1 = M_c0 . p  (chunk0 warps; p broadcast from smem, per-lane dot)
    if (wid < 2) {
        const float* kT = s_p + (my_is_e ? HALF_ : 0);   // reuse LOADK32 base
        ull pv[16];
        LOADK32(pv, 0);
        ull a0 = mul2(m[0], pv[0]),  a1 = mul2(m[1], pv[1]);
        ull a2 = mul2(m[2], pv[2]),  a3 = mul2(m[3], pv[3]);
        a0 = fma2(m[4],  pv[4],  a0); a1 = fma2(m[5],  pv[5],  a1);
        a2 = fma2(m[6],  pv[6],  a2); a3 = fma2(m[7],  pv[7],  a3);
        a0 = fma2(m[8],  pv[8],  a0); a1 = fma2(m[9],  pv[9],  a1);
        a2 = fma2(m[10], pv[10], a2); a3 = fma2(m[11], pv[11], a3);
        a0 = fma2(m[12], pv[12], a0); a1 = fma2(m[13], pv[13], a1);
        a2 = fma2(m[14], pv[14], a2); a3 = fma2(m[15], pv[15], a3);
        ull s01 = add2(a0, a1), s23 = add2(a2, a3);
        float2 f = unpack2(add2(s01, s23));
        s_r1[(my_is_e ? HALF_ : 0) + lane] = f.x + f.y;
    }
    __syncthreads();

    if (tid < 2 * HALF_) s_r1[tid] += s_r2[tid];
    __syncthreads();

    // out = (r @ Wrp + brp) @ Wout + bout
    if (tid < H_) {
        float acc = brp[tid];
        #pragma unroll 16
        for (int k = 0; k < 2 * HALF_; ++k) acc = fmaf(s_r1[k], Wrp[k * H_ + tid], acc);
        s_tmp[tid] = acc;
    }
    __syncthreads();
    if (tid < V_) {
        float acc = bout[tid];
        #pragma unroll 16
        for (int d = 0; d < H_; ++d) acc = fmaf(s_tmp[d], Wout[d * V_ + tid], acc);
        out[b * V_ + tid] = acc;
    }
}

// ---------------------------------------------------------------------------
extern "C" void kernel_launch(void* const* d_in, const int* in_sizes, int n_in,
                              void* d_out, int out_size)
{
    const int*   seq   = (const int*)d_in[0];
    const float* embed = (const float*)d_in[1];
    const float* W1    = (const float*)d_in[2];
    const float* b1    = (const float*)d_in[3];
    const float* W2    = (const float*)d_in[4];
    const float* b2    = (const float*)d_in[5];
    const float* gamma = (const float*)d_in[6];
    const float* beta  = (const float*)d_in[7];
    const float* Ws    = (const float*)d_in[8];
    const float* bs    = (const float*)d_in[9];
    const float* We    = (const float*)d_in[10];
    const float* be    = (const float*)d_in[11];
    const float* Wrp   = (const float*)d_in[12];
    const float* brp   = (const float*)d_in[13];
    const float* Wout  = (const float*)d_in[14];
    const float* bout  = (const float*)d_in[15];
    float* out = (float*)d_out;

    static int smem_set = 0;
    const int smem_bytes = (16384 + L_PAD + 256) * 4 + 256;
    if (!smem_set) {
        cudaFuncSetAttribute(scan_kernel,
                             cudaFuncAttributeMaxDynamicSharedMemorySize, smem_bytes);
        smem_set = 1;
    }

    build_tables<<<V_, 128>>>(embed, W1, b1, W2, b2, gamma, beta, Ws, bs, We, be);
    scan_kernel<<<B_, NT_, smem_bytes>>>(seq, Wrp, brp, Wout, bout, out);
}

// round 13
// speedup vs baseline: 1.0901x; 1.0901x over previous
#include <cuda_runtime.h>

#define B_ 128
#define L_ 4096
#define H_ 64
#define V_ 64
#define HALF_ 32
#define C1 0.05f
#define LN_EPS 1e-5f
#define REV_PAD 4112
#define NT_ 256

typedef unsigned long long ull;

// Token-indexed tables (V=64): g_hs/g_he pre-scaled by (1-ALPHA)=C1.
__device__ float g_hs[V_ * HALF_];
__device__ float g_he[V_ * HALF_];
__device__ float g_ks[V_ * HALF_];
__device__ float g_ke[V_ * HALF_];
__device__ float g_Gs[V_ * V_];
__device__ float g_Ge[V_ * V_];

// ---------------- packed f32x2 helpers ----------------
__device__ __forceinline__ ull fma2(ull a, ull b, ull c) {
    ull d; asm("fma.rn.f32x2 %0,%1,%2,%3;" : "=l"(d) : "l"(a), "l"(b), "l"(c)); return d;
}
__device__ __forceinline__ ull mul2(ull a, ull b) {
    ull d; asm("mul.rn.f32x2 %0,%1,%2;" : "=l"(d) : "l"(a), "l"(b)); return d;
}
__device__ __forceinline__ ull add2(ull a, ull b) {
    ull d; asm("add.rn.f32x2 %0,%1,%2;" : "=l"(d) : "l"(a), "l"(b)); return d;
}
__device__ __forceinline__ ull pack2(float x) {
    ull d; asm("mov.b64 %0,{%1,%1};" : "=l"(d) : "f"(x)); return d;
}
__device__ __forceinline__ float2 unpack2(ull v) {
    float2 r; asm("mov.b64 {%0,%1},%2;" : "=f"(r.x), "=f"(r.y) : "l"(v)); return r;
}

// ---------------------------------------------------------------------------
// Kernel 1: per-token precompute. grid=64 (token), block=128.
// ---------------------------------------------------------------------------
__global__ void build_tables(const float* __restrict__ embed,
                             const float* __restrict__ W1, const float* __restrict__ b1,
                             const float* __restrict__ W2, const float* __restrict__ b2,
                             const float* __restrict__ gamma, const float* __restrict__ beta,
                             const float* __restrict__ Ws, const float* __restrict__ bs,
                             const float* __restrict__ We, const float* __restrict__ be)
{
    __shared__ float s_e[H_];
    __shared__ float s_a[2 * H_];
    __shared__ float s_x[H_];
    __shared__ float s_h[H_];
    __shared__ float s_mu, s_rstd;

    int tok = blockIdx.x;
    int tid = threadIdx.x;

    if (tid < H_) s_e[tid] = embed[tok * H_ + tid];
    __syncthreads();

    {
        float acc = b1[tid];
        #pragma unroll 32
        for (int h = 0; h < H_; ++h) acc = fmaf(s_e[h], __ldg(W1 + h * 2 * H_ + tid), acc);
        s_a[tid] = fmaxf(acc, 0.0f);
    }
    __syncthreads();

    if (tid < H_) {
        float acc = b2[tid];
        #pragma unroll 32
        for (int k = 0; k < 2 * H_; ++k) acc = fmaf(s_a[k], __ldg(W2 + k * H_ + tid), acc);
        s_x[tid] = s_e[tid] + acc;
    }
    __syncthreads();

    if (tid < 32) {
        float v = s_x[tid] + s_x[tid + 32];
        #pragma unroll
        for (int m = 16; m > 0; m >>= 1) v += __shfl_xor_sync(0xffffffffu, v, m);
        const float mu = v * (1.0f / H_);
        float d0 = s_x[tid] - mu, d1 = s_x[tid + 32] - mu;
        float vv = fmaf(d0, d0, d1 * d1);
        #pragma unroll
        for (int m = 16; m > 0; m >>= 1) vv += __shfl_xor_sync(0xffffffffu, vv, m);
        if (tid == 0) {
            s_mu = mu;
            s_rstd = rsqrtf(vv * (1.0f / H_) + LN_EPS);
        }
    }
    __syncthreads();

    if (tid < H_) s_h[tid] = (s_x[tid] - s_mu) * s_rstd * gamma[tid] + beta[tid];
    __syncthreads();

    int wid = tid >> 5, lane = tid & 31;
    if (wid == 0) {
        float acc = bs[lane];
        #pragma unroll 32
        for (int j = 0; j < H_; ++j) acc = fmaf(s_h[j], __ldg(Ws + j * HALF_ + lane), acc);
        float ss = acc * acc;
        #pragma unroll
        for (int m = 16; m > 0; m >>= 1) ss += __shfl_xor_sync(0xffffffffu, ss, m);
        float n = fmaxf(sqrtf(ss), 1e-12f);
        g_hs[tok * HALF_ + lane] = C1 * acc;
        g_ks[tok * HALF_ + lane] = acc / n;
    } else if (wid == 1) {
        float acc = be[lane];
        #pragma unroll 32
        for (int j = 0; j < H_; ++j) acc = fmaf(s_h[j], __ldg(We + j * HALF_ + lane), acc);
        float ss = acc * acc;
        #pragma unroll
        for (int m = 16; m > 0; m >>= 1) ss += __shfl_xor_sync(0xffffffffu, ss, m);
        float n = fmaxf(sqrtf(ss), 1e-12f);
        g_he[tok * HALF_ + lane] = C1 * acc;
        g_ke[tok * HALF_ + lane] = acc / n;
    }
}

// ---------------------------------------------------------------------------
// Kernel 1b: 64x64 key Gram matrices. grid=64, block=64.
// ---------------------------------------------------------------------------
__global__ void build_gram()
{
    int a = blockIdx.x;
    int b = threadIdx.x;
    float ss = 0.f, se = 0.f;
    #pragma unroll
    for (int j = 0; j < HALF_; ++j) {
        ss = fmaf(g_ks[a * HALF_ + j], g_ks[b * HALF_ + j], ss);
        se = fmaf(g_ke[a * HALF_ + j], g_ke[b * HALF_ + j], se);
    }
    g_Gs[a * V_ + b] = ss;
    g_Ge[a * V_ + b] = se;
}

// 8 floats (quad slice) of token key row; col0 = (lane&3)*8 floats
#define LOADK8(D, TOK) { \
    const ulonglong2* p_ = (const ulonglong2*)(kT + ((TOK) << 5) + col0); \
    ulonglong2 a_ = p_[0], b_ = p_[1]; \
    D##0 = a_.x; D##1 = a_.y; D##2 = b_.x; D##3 = b_.y; }

// ---------------------------------------------------------------------------
// Kernel 2: backward-vector formulation.
//   r = M_{L-1} q = sum_t c_t (k_t . u_{t+1}) h_t,
//   u_{t} = u_{t+1} - c_t k_t (k_t . u_{t+1}),   u_{L-1} = q.
// Per-token scalar accumulation: S[v] += wd_t (wd = sc*w), r = sum_v S[v] g_h[v].
// 2 working warps (w0 = s on SMSP0, w1 = e on SMSP1); u over lane quads.
// Defer-4 pipeline: partials for raw_{j+4} = k_{j+4}.u^{j+1} issued at iter j;
// reduced at iter j+2; corrections: 2 in x (wd_{j-2}, wd_{j-1}), 1 on chain.
// Serial chain per iter: ONE FFMA.
// ---------------------------------------------------------------------------
__global__ __launch_bounds__(NT_, 1)
void scan_kernel(const int* __restrict__ seq,
                 const float* __restrict__ Wrp, const float* __restrict__ brp,
                 const float* __restrict__ Wout, const float* __restrict__ bout,
                 float* __restrict__ out)
{
    extern __shared__ float sm[];
    float* s_ks = sm;                          // 2048
    float* s_ke = sm + 2048;                   // 2048
    float* s_hs = sm + 4096;                   // 2048
    float* s_he = sm + 6144;                   // 2048
    float* s_Gs = sm + 8192;                   // 4096
    float* s_Ge = sm + 12288;                  // 4096
    int*   s_rev = (int*)(sm + 16384);         // REV_PAD ints
    float* s_S   = sm + 16384 + REV_PAD;       // 128 (S_s | S_e)
    float* s_r1  = s_S + 128;                  // 64
    float* s_tmp = s_r1 + 64;                  // 64

    const int b = blockIdx.x;
    const int tid = threadIdx.x;
    const int wid = tid >> 5;
    const int lane = tid & 31;

    // ---- stage: reversed sequence (+4 dummy head, zero tail), tables ----
    {
        const int* seqb = seq + b * L_;
        for (int i = tid; i <= L_ - 2; i += NT_) s_rev[4 + i] = seqb[L_ - 2 - i];
        if (tid < 4) s_rev[tid] = seqb[L_ - 1];
        if (tid < REV_PAD - (L_ + 3)) s_rev[L_ + 3 + tid] = 0;
    }
    for (int k = tid; k < V_ * HALF_; k += NT_) {
        s_ks[k] = g_ks[k];
        s_ke[k] = g_ke[k];
        s_hs[k] = g_hs[k];
        s_he[k] = g_he[k];
    }
    for (int k = tid; k < V_ * V_; k += NT_) {
        s_Gs[k] = g_Gs[k];
        s_Ge[k] = g_Ge[k];
    }
    if (tid < 128) s_S[tid] = 0.0f;
    __syncthreads();

    if (wid < 2) {
        const bool is_e = (wid == 1);
        const float* kT = is_e ? s_ke : s_ks;
        const float* gT = is_e ? s_Ge : s_Gs;
        float* pS = s_S + (is_e ? 64 : 0);
        const int col0 = (lane & 3) << 3;
        const float invL = 1.0f / (float)L_;
        const float scFirst = is_e ? (float)(L_ - 1) * invL : 1.0f;
        const float scStep  = is_e ? -invL : 0.0f;

        // ---- state init ----
        ull u0, u1, u2, u3;
        ull KU00=0,KU01=0,KU02=0,KU03=0, KU10=0,KU11=0,KU12=0,KU13=0;
        ull KN00=0,KN01=0,KN02=0,KN03=0, KN10=0,KN11=0,KN12=0,KN13=0;
        ull P0a=0,P0b=0,P1a=0,P1b=0,P2a=0,P2b=0,P3a=0,P3b=0;
        float rw0=0.f, rw1=0.f, rw2=0.f, rw3=0.f;
        float x0=0.f, x1=0.f, cg0=0.f, cg1=0.f;
        float wd1=0.f, wd2=0.f;
        float scx = 0.f;

        int tm2 = s_rev[0], tm1 = s_rev[0], tc = s_rev[0];
        int tp1 = s_rev[1], tp2 = s_rev[2], tp3 = s_rev[3];
        int tp4 = s_rev[4], tp5 = s_rev[5];

        LOADK8(u, s_rev[0]);         // u = q (normalized key of last token)
        { const int t4 = s_rev[4]; LOADK8(KN0, t4); }   // partial key for peel 0

        const int* rp = s_rev;

        // Body for iteration j (residue R):
        //  consumes x/cg (XI), produces (XO); update key KUc (k_j, preloaded),
        //  partial key KNc (k_{j+4}, preloaded); loads KUl <- k(tp1), KNl <- k(tp5);
        //  partials -> PW pair; reduce PR pair -> RWW; x uses RWR (raw_{j+1}).
        #define BODY(XI, CGI, XO, CGO, KUc, KUl, KNc, KNl, PWa, PWb, PRa, PRb, RWW, RWR, SCUPD, RPOFF) { \
            /* chain: wd_j */ \
            const float wdn_ = fmaf(-wd1, CGI, XI); \
            /* S accumulation (all lanes same addr/value: broadcast + collapsed write) */ \
            pS[tc] += wdn_; \
            /* u update with k_j */ \
            const ull d2_ = pack2(-C1 * wdn_); \
            u0 = fma2(d2_, KUc##0, u0); u1 = fma2(d2_, KUc##1, u1); \
            u2 = fma2(d2_, KUc##2, u2); u3 = fma2(d2_, KUc##3, u3); \
            /* partials for raw_{j+4} on u^{j+1} with k_{j+4} */ \
            PWa = mul2(u0, KNc##0); PWb = mul2(u1, KNc##1); \
            PWa = fma2(u2, KNc##2, PWa); PWb = fma2(u3, KNc##3, PWb); \
            /* prefetch next iter's keys */ \
            LOADK8(KUl, tp1); \
            LOADK8(KNl, tp5); \
            /* reduce pair issued 2 iters ago -> raw_{j+2} */ \
            { ull rs_ = add2(PRa, PRb); \
              float2 rf_ = unpack2(rs_); \
              float rr_ = rf_.x + rf_.y; \
              rr_ += __shfl_xor_sync(0xffffffffu, rr_, 1); \
              rr_ += __shfl_xor_sync(0xffffffffu, rr_, 2); \
              RWW = rr_; } \
            /* build x_{j+1}, cg_{j+1} */ \
            SCUPD; \
            { const float cs_ = C1 * scx; \
              const int gb_ = tp1 << 6; \
              const float Ga_ = gT[gb_ + tm2]; \
              const float Gb_ = gT[gb_ + tm1]; \
              const float Gc_ = gT[gb_ + tc]; \
              float tq_ = wd2 * Ga_; \
              tq_ = fmaf(wd1, Gb_, tq_); \
              XO = fmaf(-cs_, tq_, scx * RWR); \
              CGO = cs_ * Gc_; } \
            /* token prefetch + shifts */ \
            const int tnew_ = rp[RPOFF]; \
            tm2 = tm1; tm1 = tc; tc = tp1; tp1 = tp2; tp2 = tp3; tp3 = tp4; \
            tp4 = tp5; tp5 = tnew_; \
            wd2 = wd1; wd1 = wdn_; }

        // ---- 4 dummy peels (sc forced; wd stays 0, u untouched) ----
        BODY(x0, cg0, x1, cg1, KU0, KU1, KN0, KN1, P0a, P0b, P2a, P2b, rw2, rw1, scx = 0.0f, 6);
        BODY(x1, cg1, x0, cg0, KU1, KU0, KN1, KN0, P1a, P1b, P3a, P3b, rw3, rw2, scx = 0.0f, 7);
        BODY(x0, cg0, x1, cg1, KU0, KU1, KN0, KN1, P2a, P2b, P0a, P0b, rw0, rw3, scx = 0.0f, 8);
        BODY(x1, cg1, x0, cg0, KU1, KU0, KN1, KN0, P3a, P3b, P1a, P1b, rw1, rw0, scx = scFirst, 9);
        rp += 4;

        // ---- main: 1023 blocks of 4 (jj = 4 .. 4095) ----
        #pragma unroll 1
        for (int blk = 0; blk < 1023; ++blk) {
            BODY(x0, cg0, x1, cg1, KU0, KU1, KN0, KN1, P0a, P0b, P2a, P2b, rw2, rw1, scx += scStep, 6);
            BODY(x1, cg1, x0, cg0, KU1, KU0, KN1, KN0, P1a, P1b, P3a, P3b, rw3, rw2, scx += scStep, 7);
            BODY(x0, cg0, x1, cg1, KU0, KU1, KN0, KN1, P2a, P2b, P0a, P0b, rw0, rw3, scx += scStep, 8);
            BODY(x1, cg1, x0, cg0, KU1, KU0, KN1, KN0, P3a, P3b, P1a, P1b, rw1, rw0, scx += scStep, 9);
            rp += 4;
        }
        // ---- tails: jj = 4096, 4097, 4098 ----
        BODY(x0, cg0, x1, cg1, KU0, KU1, KN0, KN1, P0a, P0b, P2a, P2b, rw2, rw1, scx += scStep, 6);
        BODY(x1, cg1, x0, cg0, KU1, KU0, KN1, KN0, P1a, P1b, P3a, P3b, rw3, rw2, scx += scStep, 7);
        BODY(x0, cg0, x1, cg1, KU0, KU1, KN0, KN1, P2a, P2b, P0a, P0b, rw0, rw3, scx += scStep, 8);
        #undef BODY
    }
    __syncthreads();

    // ---- r[i] = sum_v S[v] * g_h[v, i]  (g_h pre-scaled by C1) ----
    if (tid < 64) {
        const bool ise = tid >= 32;
        const int i = tid & 31;
        const float* hT = ise ? s_he : s_hs;
        const float* Sv = s_S + (ise ? 64 : 0);
        float acc = 0.f;
        #pragma unroll 16
        for (int v = 0; v < V_; ++v) acc = fmaf(Sv[v], hT[(v << 5) + i], acc);
        s_r1[tid] = acc;
    }
    __syncthreads();

    // out = (r @ Wrp + brp) @ Wout + bout
    if (tid < H_) {
        float acc = brp[tid];
        #pragma unroll 16
        for (int k = 0; k < 2 * HALF_; ++k) acc = fmaf(s_r1[k], Wrp[k * H_ + tid], acc);
        s_tmp[tid] = acc;
    }
    __syncthreads();
    if (tid < V_) {
        float acc = bout[tid];
        #pragma unroll 16
        for (int d = 0; d < H_; ++d) acc = fmaf(s_tmp[d], Wout[d * V_ + tid], acc);
        out[b * V_ + tid] = acc;
    }
}

// ---------------------------------------------------------------------------
extern "C" void kernel_launch(void* const* d_in, const int* in_sizes, int n_in,
                              void* d_out, int out_size)
{
    const int*   seq   = (const int*)d_in[0];
    const float* embed = (const float*)d_in[1];
    const float* W1    = (const float*)d_in[2];
    const float* b1    = (const float*)d_in[3];
    const float* W2    = (const float*)d_in[4];
    const float* b2    = (const float*)d_in[5];
    const float* gamma = (const float*)d_in[6];
    const float* beta  = (const float*)d_in[7];
    const float* Ws    = (const float*)d_in[8];
    const float* bs    = (const float*)d_in[9];
    const float* We    = (const float*)d_in[10];
    const float* be    = (const float*)d_in[11];
    const float* Wrp   = (const float*)d_in[12];
    const float* brp   = (const float*)d_in[13];
    const float* Wout  = (const float*)d_in[14];
    const float* bout  = (const float*)d_in[15];
    float* out = (float*)d_out;

    static int smem_set = 0;
    const int smem_bytes = (16384 + REV_PAD + 128 + 128) * 4 + 256;
    if (!smem_set) {
        cudaFuncSetAttribute(scan_kernel,
                             cudaFuncAttributeMaxDynamicSharedMemorySize, smem_bytes);
        smem_set = 1;
    }

    build_tables<<<V_, 128>>>(embed, W1, b1, W2, b2, gamma, beta, Ws, bs, We, be);
    build_gram<<<V_, V_>>>();
    scan_kernel<<<B_, NT_, smem_bytes>>>(seq, Wrp, brp, Wout, bout, out);
}

// round 14
// speedup vs baseline: 1.2989x; 1.1915x over previous
#include <cuda_runtime.h>

#define B_ 128
#define L_ 4096
#define H_ 64
#define V_ 64
#define HALF_ 32
#define C1 0.05f
#define LN_EPS 1e-5f
#define REV_PAD 4112
#define NT_ 256

typedef unsigned long long ull;

// Token-indexed tables (V=64): g_hs/g_he pre-scaled by (1-ALPHA)=C1.
__device__ float g_hs[V_ * HALF_];
__device__ float g_he[V_ * HALF_];
__device__ float g_ks[V_ * HALF_];
__device__ float g_ke[V_ * HALF_];
__device__ float g_Gs[V_ * V_];
__device__ float g_Ge[V_ * V_];

// ---------------- packed f32x2 helpers ----------------
__device__ __forceinline__ ull fma2(ull a, ull b, ull c) {
    ull d; asm("fma.rn.f32x2 %0,%1,%2,%3;" : "=l"(d) : "l"(a), "l"(b), "l"(c)); return d;
}
__device__ __forceinline__ ull mul2(ull a, ull b) {
    ull d; asm("mul.rn.f32x2 %0,%1,%2;" : "=l"(d) : "l"(a), "l"(b)); return d;
}
__device__ __forceinline__ ull add2(ull a, ull b) {
    ull d; asm("add.rn.f32x2 %0,%1,%2;" : "=l"(d) : "l"(a), "l"(b)); return d;
}
__device__ __forceinline__ ull pack2(float x) {
    ull d; asm("mov.b64 %0,{%1,%1};" : "=l"(d) : "f"(x)); return d;
}
__device__ __forceinline__ float2 unpack2(ull v) {
    float2 r; asm("mov.b64 {%0,%1},%2;" : "=f"(r.x), "=f"(r.y) : "l"(v)); return r;
}

// ---------------------------------------------------------------------------
// Kernel 1: per-token precompute. grid=64 (token), block=128.
// ---------------------------------------------------------------------------
__global__ void build_tables(const float* __restrict__ embed,
                             const float* __restrict__ W1, const float* __restrict__ b1,
                             const float* __restrict__ W2, const float* __restrict__ b2,
                             const float* __restrict__ gamma, const float* __restrict__ beta,
                             const float* __restrict__ Ws, const float* __restrict__ bs,
                             const float* __restrict__ We, const float* __restrict__ be)
{
    __shared__ float s_e[H_];
    __shared__ float s_a[2 * H_];
    __shared__ float s_x[H_];
    __shared__ float s_h[H_];
    __shared__ float s_mu, s_rstd;

    int tok = blockIdx.x;
    int tid = threadIdx.x;

    if (tid < H_) s_e[tid] = embed[tok * H_ + tid];
    __syncthreads();

    {
        float acc = b1[tid];
        #pragma unroll 32
        for (int h = 0; h < H_; ++h) acc = fmaf(s_e[h], __ldg(W1 + h * 2 * H_ + tid), acc);
        s_a[tid] = fmaxf(acc, 0.0f);
    }
    __syncthreads();

    if (tid < H_) {
        float acc = b2[tid];
        #pragma unroll 32
        for (int k = 0; k < 2 * H_; ++k) acc = fmaf(s_a[k], __ldg(W2 + k * H_ + tid), acc);
        s_x[tid] = s_e[tid] + acc;
    }
    __syncthreads();

    if (tid < 32) {
        float v = s_x[tid] + s_x[tid + 32];
        #pragma unroll
        for (int m = 16; m > 0; m >>= 1) v += __shfl_xor_sync(0xffffffffu, v, m);
        const float mu = v * (1.0f / H_);
        float d0 = s_x[tid] - mu, d1 = s_x[tid + 32] - mu;
        float vv = fmaf(d0, d0, d1 * d1);
        #pragma unroll
        for (int m = 16; m > 0; m >>= 1) vv += __shfl_xor_sync(0xffffffffu, vv, m);
        if (tid == 0) {
            s_mu = mu;
            s_rstd = rsqrtf(vv * (1.0f / H_) + LN_EPS);
        }
    }
    __syncthreads();

    if (tid < H_) s_h[tid] = (s_x[tid] - s_mu) * s_rstd * gamma[tid] + beta[tid];
    __syncthreads();

    int wid = tid >> 5, lane = tid & 31;
    if (wid == 0) {
        float acc = bs[lane];
        #pragma unroll 32
        for (int j = 0; j < H_; ++j) acc = fmaf(s_h[j], __ldg(Ws + j * HALF_ + lane), acc);
        float ss = acc * acc;
        #pragma unroll
        for (int m = 16; m > 0; m >>= 1) ss += __shfl_xor_sync(0xffffffffu, ss, m);
        float n = fmaxf(sqrtf(ss), 1e-12f);
        g_hs[tok * HALF_ + lane] = C1 * acc;
        g_ks[tok * HALF_ + lane] = acc / n;
    } else if (wid == 1) {
        float acc = be[lane];
        #pragma unroll 32
        for (int j = 0; j < H_; ++j) acc = fmaf(s_h[j], __ldg(We + j * HALF_ + lane), acc);
        float ss = acc * acc;
        #pragma unroll
        for (int m = 16; m > 0; m >>= 1) ss += __shfl_xor_sync(0xffffffffu, ss, m);
        float n = fmaxf(sqrtf(ss), 1e-12f);
        g_he[tok * HALF_ + lane] = C1 * acc;
        g_ke[tok * HALF_ + lane] = acc / n;
    }
}

// ---------------------------------------------------------------------------
// Kernel 1b: 64x64 key Gram matrices. grid=64, block=64.
// ---------------------------------------------------------------------------
__global__ void build_gram()
{
    int a = blockIdx.x;
    int b = threadIdx.x;
    float ss = 0.f, se = 0.f;
    #pragma unroll
    for (int j = 0; j < HALF_; ++j) {
        ss = fmaf(g_ks[a * HALF_ + j], g_ks[b * HALF_ + j], ss);
        se = fmaf(g_ke[a * HALF_ + j], g_ke[b * HALF_ + j], se);
    }
    g_Gs[a * V_ + b] = ss;
    g_Ge[a * V_ + b] = se;
}

// 8 floats (quad slice) of token key row; col0 = (lane&3)*8 floats
#define LOADK8(D, TOK) { \
    const ulonglong2* p_ = (const ulonglong2*)(kT + ((TOK) << 5) + col0); \
    ulonglong2 a_ = p_[0], b_ = p_[1]; \
    D##0 = a_.x; D##1 = a_.y; D##2 = b_.x; D##3 = b_.y; }

// ---------------------------------------------------------------------------
// Kernel 2: backward-vector formulation.
//   r = M_{L-1} q = sum_t c_t (k_t . u_{t+1}) h_t,
//   u_{t} = u_{t+1} - c_t k_t (k_t . u_{t+1}),   u_{L-1} = q.
// Per-token scalar accumulation IN REGISTERS (lane-sliced, predicated):
//   lane owns tokens {lane, lane+32}; r = sum_v S[v] g_h[v] at the end.
// 2 working warps (w0 = s on SMSP0, w1 = e on SMSP1); u over lane quads.
// Defer-4 pipeline: partials for raw_{j+4} = k_{j+4}.u^{j+1} issued at iter j;
// reduced at iter j+2; corrections: 2 in x (wd_{j-2}, wd_{j-1}), 1 on chain.
// Serial chain per iter: ONE FFMA.
// ---------------------------------------------------------------------------
__global__ __launch_bounds__(NT_, 1)
void scan_kernel(const int* __restrict__ seq,
                 const float* __restrict__ Wrp, const float* __restrict__ brp,
                 const float* __restrict__ Wout, const float* __restrict__ bout,
                 float* __restrict__ out)
{
    extern __shared__ float sm[];
    float* s_ks = sm;                          // 2048
    float* s_ke = sm + 2048;                   // 2048
    float* s_hs = sm + 4096;                   // 2048
    float* s_he = sm + 6144;                   // 2048
    float* s_Gs = sm + 8192;                   // 4096
    float* s_Ge = sm + 12288;                  // 4096
    int*   s_rev = (int*)(sm + 16384);         // REV_PAD ints
    float* s_S   = sm + 16384 + REV_PAD;       // 128 (S_s | S_e)
    float* s_r1  = s_S + 128;                  // 64
    float* s_tmp = s_r1 + 64;                  // 64

    const int b = blockIdx.x;
    const int tid = threadIdx.x;
    const int wid = tid >> 5;
    const int lane = tid & 31;

    // ---- stage: reversed sequence (+4 dummy head, zero tail), tables ----
    {
        const int* seqb = seq + b * L_;
        for (int i = tid; i <= L_ - 2; i += NT_) s_rev[4 + i] = seqb[L_ - 2 - i];
        if (tid < 4) s_rev[tid] = seqb[L_ - 1];
        if (tid < REV_PAD - (L_ + 3)) s_rev[L_ + 3 + tid] = 0;
    }
    for (int k = tid; k < V_ * HALF_; k += NT_) {
        s_ks[k] = g_ks[k];
        s_ke[k] = g_ke[k];
        s_hs[k] = g_hs[k];
        s_he[k] = g_he[k];
    }
    for (int k = tid; k < V_ * V_; k += NT_) {
        s_Gs[k] = g_Gs[k];
        s_Ge[k] = g_Ge[k];
    }
    __syncthreads();

    if (wid < 2) {
        const bool is_e = (wid == 1);
        const float* kT = is_e ? s_ke : s_ks;
        const float* gT = is_e ? s_Ge : s_Gs;
        float* pS = s_S + (is_e ? 64 : 0);
        const int col0 = (lane & 3) << 3;
        const int laneB = lane + 32;
        const float invL = 1.0f / (float)L_;
        const float scFirst = is_e ? (float)(L_ - 1) * invL : 1.0f;
        const float scStep  = is_e ? -invL : 0.0f;
        const float csFirst = C1 * scFirst;
        const float csStep  = C1 * scStep;

        // ---- state init ----
        ull u0, u1, u2, u3;
        ull KU00=0,KU01=0,KU02=0,KU03=0, KU10=0,KU11=0,KU12=0,KU13=0;
        ull KN00=0,KN01=0,KN02=0,KN03=0, KN10=0,KN11=0,KN12=0,KN13=0;
        ull P0a=0,P0b=0,P1a=0,P1b=0,P2a=0,P2b=0,P3a=0,P3b=0;
        float rw0=0.f, rw1=0.f, rw2=0.f, rw3=0.f;
        float x0=0.f, x1=0.f, cg0=0.f, cg1=0.f;
        float wd1=0.f, wd2=0.f;
        float scx = 0.f, csx = 0.f;
        float saccA = 0.f, saccB = 0.f;        // S for tokens lane, lane+32

        int tm2 = s_rev[0], tm1 = s_rev[0], tc = s_rev[0];
        int tp1 = s_rev[1], tp2 = s_rev[2], tp3 = s_rev[3];
        int tp4 = s_rev[4], tp5 = s_rev[5];

        LOADK8(u, s_rev[0]);         // u = q (normalized key of last token)
        { const int t4 = s_rev[4]; LOADK8(KN0, t4); }   // partial key for peel 0

        const int* rp = s_rev;

        // Body for iteration j:
        //  consumes x/cg (XI); update key KUc (k_j, preloaded), partial key
        //  KNc (k_{j+4}, preloaded); loads KUl <- k(tp1), KNl <- k(tp5);
        //  partials -> PW pair; reduce PR pair -> RWW; x uses RWR (raw_{j+1}).
        #define BODY(XI, CGI, XO, CGO, KUc, KUl, KNc, KNl, PWa, PWb, PRa, PRb, RWW, RWR, SCUPD, RPOFF) { \
            /* chain: wd_j (1 FFMA) */ \
            const float wdn_ = fmaf(-wd1, CGI, XI); \
            /* S accumulation: pure-register, predicated, off-chain */ \
            saccA += (tc == lane)  ? wdn_ : 0.0f; \
            saccB += (tc == laneB) ? wdn_ : 0.0f; \
            /* u update with k_j */ \
            const ull d2_ = pack2(-C1 * wdn_); \
            u0 = fma2(d2_, KUc##0, u0); u1 = fma2(d2_, KUc##1, u1); \
            u2 = fma2(d2_, KUc##2, u2); u3 = fma2(d2_, KUc##3, u3); \
            /* partials for raw_{j+4} on u^{j+1} with k_{j+4} */ \
            PWa = mul2(u0, KNc##0); PWb = mul2(u1, KNc##1); \
            PWa = fma2(u2, KNc##2, PWa); PWb = fma2(u3, KNc##3, PWb); \
            /* prefetch next iter's keys */ \
            LOADK8(KUl, tp1); \
            LOADK8(KNl, tp5); \
            /* reduce pair issued 2 iters ago -> raw_{j+2} */ \
            { ull rs_ = add2(PRa, PRb); \
              float2 rf_ = unpack2(rs_); \
              float rr_ = rf_.x + rf_.y; \
              rr_ += __shfl_xor_sync(0xffffffffu, rr_, 1); \
              rr_ += __shfl_xor_sync(0xffffffffu, rr_, 2); \
              RWW = rr_; } \
            /* build x_{j+1}, cg_{j+1} */ \
            SCUPD; \
            { const int gb_ = tp1 << 6; \
              const float Ga_ = gT[gb_ + tm2]; \
              const float Gb_ = gT[gb_ + tm1]; \
              const float Gc_ = gT[gb_ + tc]; \
              float tq_ = wd2 * Ga_; \
              tq_ = fmaf(wd1, Gb_, tq_); \
              XO = fmaf(-csx, tq_, scx * RWR); \
              CGO = csx * Gc_; } \
            /* token prefetch + shifts */ \
            const int tnew_ = rp[RPOFF]; \
            tm2 = tm1; tm1 = tc; tc = tp1; tp1 = tp2; tp2 = tp3; tp3 = tp4; \
            tp4 = tp5; tp5 = tnew_; \
            wd2 = wd1; wd1 = wdn_; }

        // ---- 4 dummy peels (sc forced; wd stays 0, u untouched) ----
        BODY(x0, cg0, x1, cg1, KU0, KU1, KN0, KN1, P0a, P0b, P2a, P2b, rw2, rw1, { scx = 0.0f; csx = 0.0f; }, 6);
        BODY(x1, cg1, x0, cg0, KU1, KU0, KN1, KN0, P1a, P1b, P3a, P3b, rw3, rw2, { scx = 0.0f; csx = 0.0f; }, 7);
        BODY(x0, cg0, x1, cg1, KU0, KU1, KN0, KN1, P2a, P2b, P0a, P0b, rw0, rw3, { scx = 0.0f; csx = 0.0f; }, 8);
        BODY(x1, cg1, x0, cg0, KU1, KU0, KN1, KN0, P3a, P3b, P1a, P1b, rw1, rw0, { scx = scFirst; csx = csFirst; }, 9);
        rp += 4;

        // ---- main: 1023 blocks of 4 (jj = 4 .. 4095) ----
        #pragma unroll 1
        for (int blk = 0; blk < 1023; ++blk) {
            BODY(x0, cg0, x1, cg1, KU0, KU1, KN0, KN1, P0a, P0b, P2a, P2b, rw2, rw1, { scx += scStep; csx += csStep; }, 6);
            BODY(x1, cg1, x0, cg0, KU1, KU0, KN1, KN0, P1a, P1b, P3a, P3b, rw3, rw2, { scx += scStep; csx += csStep; }, 7);
            BODY(x0, cg0, x1, cg1, KU0, KU1, KN0, KN1, P2a, P2b, P0a, P0b, rw0, rw3, { scx += scStep; csx += csStep; }, 8);
            BODY(x1, cg1, x0, cg0, KU1, KU0, KN1, KN0, P3a, P3b, P1a, P1b, rw1, rw0, { scx += scStep; csx += csStep; }, 9);
            rp += 4;
        }
        // ---- tails: jj = 4096, 4097, 4098 ----
        BODY(x0, cg0, x1, cg1, KU0, KU1, KN0, KN1, P0a, P0b, P2a, P2b, rw2, rw1, { scx += scStep; csx += csStep; }, 6);
        BODY(x1, cg1, x0, cg0, KU1, KU0, KN1, KN0, P1a, P1b, P3a, P3b, rw3, rw2, { scx += scStep; csx += csStep; }, 7);
        BODY(x0, cg0, x1, cg1, KU0, KU1, KN0, KN1, P2a, P2b, P0a, P0b, rw0, rw3, { scx += scStep; csx += csStep; }, 8);
        #undef BODY

        // ---- spill register S to smem (one STS pair per lane) ----
        pS[lane]  = saccA;
        pS[laneB] = saccB;
    }
    __syncthreads();

    // ---- r[i] = sum_v S[v] * g_h[v, i]  (g_h pre-scaled by C1) ----
    if (tid < 64) {
        const bool ise = tid >= 32;
        const int i = tid & 31;
        const float* hT = ise ? s_he : s_hs;
        const float* Sv = s_S + (ise ? 64 : 0);
        float acc = 0.f;
        #pragma unroll 16
        for (int v = 0; v < V_; ++v) acc = fmaf(Sv[v], hT[(v << 5) + i], acc);
        s_r1[tid] = acc;
    }
    __syncthreads();

    // out = (r @ Wrp + brp) @ Wout + bout
    if (tid < H_) {
        float acc = brp[tid];
        #pragma unroll 16
        for (int k = 0; k < 2 * HALF_; ++k) acc = fmaf(s_r1[k], Wrp[k * H_ + tid], acc);
        s_tmp[tid] = acc;
    }
    __syncthreads();
    if (tid < V_) {
        float acc = bout[tid];
        #pragma unroll 16
        for (int d = 0; d < H_; ++d) acc = fmaf(s_tmp[d], Wout[d * V_ + tid], acc);
        out[b * V_ + tid] = acc;
    }
}

// ---------------------------------------------------------------------------
extern "C" void kernel_launch(void* const* d_in, const int* in_sizes, int n_in,
                              void* d_out, int out_size)
{
    const int*   seq   = (const int*)d_in[0];
    const float* embed = (const float*)d_in[1];
    const float* W1    = (const float*)d_in[2];
    const float* b1    = (const float*)d_in[3];
    const float* W2    = (const float*)d_in[4];
    const float* b2    = (const float*)d_in[5];
    const float* gamma = (const float*)d_in[6];
    const float* beta  = (const float*)d_in[7];
    const float* Ws    = (const float*)d_in[8];
    const float* bs    = (const float*)d_in[9];
    const float* We    = (const float*)d_in[10];
    const float* be    = (const float*)d_in[11];
    const float* Wrp   = (const float*)d_in[12];
    const float* brp   = (const float*)d_in[13];
    const float* Wout  = (const float*)d_in[14];
    const float* bout  = (const float*)d_in[15];
    float* out = (float*)d_out;

    static int smem_set = 0;
    const int smem_bytes = (16384 + REV_PAD + 128 + 128) * 4 + 256;
    if (!smem_set) {
        cudaFuncSetAttribute(scan_kernel,
                             cudaFuncAttributeMaxDynamicSharedMemorySize, smem_bytes);
        smem_set = 1;
    }

    build_tables<<<V_, 128>>>(embed, W1, b1, W2, b2, gamma, beta, Ws, bs, We, be);
    build_gram<<<V_, V_>>>();
    scan_kernel<<<B_, NT_, smem_bytes>>>(seq, Wrp, brp, Wout, bout, out);
}

// round 15
// speedup vs baseline: 1.7657x; 1.3594x over previous
#include <cuda_runtime.h>

#define B_ 128
#define L_ 4096
#define H_ 64
#define V_ 64
#define HALF_ 32
#define C1 0.05f
#define LN_EPS 1e-5f
#define NT_ 256

typedef unsigned long long ull;

// Token-indexed tables (V=64): g_hs/g_he pre-scaled by (1-ALPHA)=C1.
__device__ float g_hs[V_ * HALF_];
__device__ float g_he[V_ * HALF_];
__device__ float g_ks[V_ * HALF_];
__device__ float g_ke[V_ * HALF_];
__device__ float g_Gs[V_ * V_];
__device__ float g_Ge[V_ * V_];

// ---------------- packed f32x2 helpers ----------------
__device__ __forceinline__ ull fma2(ull a, ull b, ull c) {
    ull d; asm("fma.rn.f32x2 %0,%1,%2,%3;" : "=l"(d) : "l"(a), "l"(b), "l"(c)); return d;
}
__device__ __forceinline__ ull mul2(ull a, ull b) {
    ull d; asm("mul.rn.f32x2 %0,%1,%2;" : "=l"(d) : "l"(a), "l"(b)); return d;
}
__device__ __forceinline__ ull pack2(float x) {
    ull d; asm("mov.b64 %0,{%1,%1};" : "=l"(d) : "f"(x)); return d;
}
__device__ __forceinline__ float2 unpack2(ull v) {
    float2 r; asm("mov.b64 {%0,%1},%2;" : "=f"(r.x), "=f"(r.y) : "l"(v)); return r;
}

// ---------------------------------------------------------------------------
// Kernel 1: per-token precompute. grid=64 (token), block=128.
// ---------------------------------------------------------------------------
__global__ void build_tables(const float* __restrict__ embed,
                             const float* __restrict__ W1, const float* __restrict__ b1,
                             const float* __restrict__ W2, const float* __restrict__ b2,
                             const float* __restrict__ gamma, const float* __restrict__ beta,
                             const float* __restrict__ Ws, const float* __restrict__ bs,
                             const float* __restrict__ We, const float* __restrict__ be)
{
    __shared__ float s_e[H_];
    __shared__ float s_a[2 * H_];
    __shared__ float s_x[H_];
    __shared__ float s_h[H_];
    __shared__ float s_mu, s_rstd;

    int tok = blockIdx.x;
    int tid = threadIdx.x;

    if (tid < H_) s_e[tid] = embed[tok * H_ + tid];
    __syncthreads();

    {
        float acc = b1[tid];
        #pragma unroll 32
        for (int h = 0; h < H_; ++h) acc = fmaf(s_e[h], __ldg(W1 + h * 2 * H_ + tid), acc);
        s_a[tid] = fmaxf(acc, 0.0f);
    }
    __syncthreads();

    if (tid < H_) {
        float acc = b2[tid];
        #pragma unroll 32
        for (int k = 0; k < 2 * H_; ++k) acc = fmaf(s_a[k], __ldg(W2 + k * H_ + tid), acc);
        s_x[tid] = s_e[tid] + acc;
    }
    __syncthreads();

    if (tid < 32) {
        float v = s_x[tid] + s_x[tid + 32];
        #pragma unroll
        for (int m = 16; m > 0; m >>= 1) v += __shfl_xor_sync(0xffffffffu, v, m);
        const float mu = v * (1.0f / H_);
        float d0 = s_x[tid] - mu, d1 = s_x[tid + 32] - mu;
        float vv = fmaf(d0, d0, d1 * d1);
        #pragma unroll
        for (int m = 16; m > 0; m >>= 1) vv += __shfl_xor_sync(0xffffffffu, vv, m);
        if (tid == 0) {
            s_mu = mu;
            s_rstd = rsqrtf(vv * (1.0f / H_) + LN_EPS);
        }
    }
    __syncthreads();

    if (tid < H_) s_h[tid] = (s_x[tid] - s_mu) * s_rstd * gamma[tid] + beta[tid];
    __syncthreads();

    int wid = tid >> 5, lane = tid & 31;
    if (wid == 0) {
        float acc = bs[lane];
        #pragma unroll 32
        for (int j = 0; j < H_; ++j) acc = fmaf(s_h[j], __ldg(Ws + j * HALF_ + lane), acc);
        float ss = acc * acc;
        #pragma unroll
        for (int m = 16; m > 0; m >>= 1) ss += __shfl_xor_sync(0xffffffffu, ss, m);
        float n = fmaxf(sqrtf(ss), 1e-12f);
        g_hs[tok * HALF_ + lane] = C1 * acc;
        g_ks[tok * HALF_ + lane] = acc / n;
    } else if (wid == 1) {
        float acc = be[lane];
        #pragma unroll 32
        for (int j = 0; j < H_; ++j) acc = fmaf(s_h[j], __ldg(We + j * HALF_ + lane), acc);
        float ss = acc * acc;
        #pragma unroll
        for (int m = 16; m > 0; m >>= 1) ss += __shfl_xor_sync(0xffffffffu, ss, m);
        float n = fmaxf(sqrtf(ss), 1e-12f);
        g_he[tok * HALF_ + lane] = C1 * acc;
        g_ke[tok * HALF_ + lane] = acc / n;
    }
}

// ---------------------------------------------------------------------------
// Kernel 1b: 64x64 key Gram matrices. grid=64, block=64.
// ---------------------------------------------------------------------------
__global__ void build_gram()
{
    int a = blockIdx.x;
    int b = threadIdx.x;
    float ss = 0.f, se = 0.f;
    #pragma unroll
    for (int j = 0; j < HALF_; ++j) {
        ss = fmaf(g_ks[a * HALF_ + j], g_ks[b * HALF_ + j], ss);
        se = fmaf(g_ke[a * HALF_ + j], g_ke[b * HALF_ + j], se);
    }
    g_Gs[a * V_ + b] = ss;
    g_Ge[a * V_ + b] = se;
}

// ---- smem layout (float offsets) ----
// keys have 65 rows (row 64 = zero pad token); Gram 65 rows x 64 cols (row 64 = 0)
#define OFF_KS   0
#define OFF_KE   2080
#define OFF_HS   4160
#define OFF_HE   6208
#define OFF_GS   8256
#define OFF_GE   12416
#define OFF_REV  16576      /* 4112 ints, 16B aligned */
#define OFF_S    20688
#define OFF_R1   20816
#define OFF_TMP  20880
#define OFF_QTOK 20944
#define SMEM_FLOATS 20948

// ---------------------------------------------------------------------------
// Kernel 2: rank-4 blocked backward-vector pass.
//   r = M_{L-1} q = sum_t sc_t w_t hhat_t;  w_t = k_t . u_{t+1};
//   u_t = u_{t+1} - C1*sc_t*w_t k_t;  u_{L-1} = q.
// Reverse steps j (t = L-2-j), blocks of 4, one pad step (token 64: zero key,
// zero Gram row). Dots for block B+1 issued at block B on pre-update u_B;
// corrected at B+1 by 16 cross-Gram terms (prev gammas) + intra-Gram chain.
// 2 scan warps (w0=s SMSP0, w1=e SMSP1); u sliced 4 floats/lane (8 slices).
// S[v] accumulated in lane-sliced registers; r = sum_v S[v] hhat_v.
// ---------------------------------------------------------------------------
__global__ __launch_bounds__(NT_, 1)
void scan_kernel(const int* __restrict__ seq,
                 const float* __restrict__ Wrp, const float* __restrict__ brp,
                 const float* __restrict__ Wout, const float* __restrict__ bout,
                 float* __restrict__ out)
{
    extern __shared__ float sm[];
    float* s_ks = sm + OFF_KS;
    float* s_ke = sm + OFF_KE;
    float* s_hs = sm + OFF_HS;
    float* s_he = sm + OFF_HE;
    float* s_Gs = sm + OFF_GS;
    float* s_Ge = sm + OFF_GE;
    int*   s_rev = (int*)(sm + OFF_REV);
    float* s_S   = sm + OFF_S;
    float* s_r1  = sm + OFF_R1;
    float* s_tmp = sm + OFF_TMP;
    int*   s_qtok = (int*)(sm + OFF_QTOK);

    const int b = blockIdx.x;
    const int tid = threadIdx.x;
    const int wid = tid >> 5;
    const int lane = tid & 31;

    // ---- stage reversed sequence + tables (65-row keys / Gram with zero row) ----
    {
        const int* seqb = seq + b * L_;
        for (int i = tid; i <= L_ - 2; i += NT_) s_rev[i] = seqb[L_ - 2 - i];
        if (tid < 17) s_rev[(L_ - 1) + tid] = 64;          // pad tokens -> zero row
        if (tid == 0) *s_qtok = seqb[L_ - 1];
    }
    for (int k = tid; k < V_ * HALF_; k += NT_) {
        s_ks[k] = g_ks[k];
        s_ke[k] = g_ke[k];
        s_hs[k] = g_hs[k];
        s_he[k] = g_he[k];
    }
    if (tid < 32) { s_ks[2048 + tid] = 0.f; s_ke[2048 + tid] = 0.f; }
    for (int k = tid; k < V_ * V_; k += NT_) {
        s_Gs[k] = g_Gs[k];
        s_Ge[k] = g_Ge[k];
    }
    if (tid < 64) { s_Gs[4096 + tid] = 0.f; s_Ge[4096 + tid] = 0.f; }
    __syncthreads();

    if (wid < 2) {
        const bool is_e = (wid == 1);
        const float* kT = is_e ? s_ke : s_ks;
        const float* gT = is_e ? s_Ge : s_Gs;
        float* pS = s_S + (is_e ? 64 : 0);
        const int col0 = (lane & 7) << 2;        // 4-float slice
        const int laneB = lane + 32;
        const float invL = 1.0f / (float)L_;
        const float st = is_e ? invL : 0.0f;
        float scB = is_e ? (float)(L_ - 1) * invL : 1.0f;
        float saccA = 0.f, saccB = 0.f;

        ull K[2][8];         // ping-pong key buffers (4 tokens x 2 ull)
        int4 T[4];           // token windows (blocks, rotating)
        float RR[2][4];      // reduced raws ping-pong
        float GP[2][4];      // gammas ping-pong
        ull u0, u1;

        // ---- prologue ----
        {
            const int tq = *s_qtok;
            const ulonglong2 v = *(const ulonglong2*)(kT + (tq << 5) + col0);
            u0 = v.x; u1 = v.y;
        }
        T[3] = make_int4(0, 0, 0, 0);            // dummy prev-block tokens
        T[0] = *(const int4*)(s_rev + 0);
        T[1] = *(const int4*)(s_rev + 4);
        #define LD2(DST0, DST1, TOK) { \
            const ulonglong2 v_ = *(const ulonglong2*)(kT + ((TOK) << 5) + col0); \
            DST0 = v_.x; DST1 = v_.y; }
        LD2(K[0][0], K[0][1], T[0].x); LD2(K[0][2], K[0][3], T[0].y);
        LD2(K[0][4], K[0][5], T[0].z); LD2(K[0][6], K[0][7], T[0].w);
        LD2(K[1][0], K[1][1], T[1].x); LD2(K[1][2], K[1][3], T[1].y);
        LD2(K[1][4], K[1][5], T[1].z); LD2(K[1][6], K[1][7], T[1].w);
        #pragma unroll
        for (int i = 0; i < 4; ++i) {
            ull P = fma2(u1, K[0][2 * i + 1], mul2(u0, K[0][2 * i]));
            float2 f = unpack2(P);
            float r = f.x + f.y;
            r += __shfl_xor_sync(0xffffffffu, r, 1);
            r += __shfl_xor_sync(0xffffffffu, r, 2);
            r += __shfl_xor_sync(0xffffffffu, r, 4);
            RR[0][i] = r;
        }
        GP[0][0] = 0.f; GP[0][1] = 0.f; GP[0][2] = 0.f; GP[0][3] = 0.f;

        // ---- main: 256 iters x 4 blocks (4096 steps = 4095 real + 1 pad) ----
        #pragma unroll 1
        for (int n = 0; n < 256; ++n) {
            const int base = n << 4;
            #pragma unroll
            for (int kk = 0; kk < 4; ++kk) {
                const int p = kk & 1;
                const int pq = p ^ 1;
                const int4 tB = T[kk];
                const int4 tP = T[(kk + 3) & 3];
                // token prefetch for block B+2 (consumed by key loads below)
                T[(kk + 2) & 3] = *(const int4*)(s_rev + base + (kk << 2) + 8);
                // Gram loads for THIS block's corrections
                const int r0 = tB.x << 6, r1 = tB.y << 6, r2 = tB.z << 6, r3 = tB.w << 6;
                const float gx00 = gT[r0 + tP.x], gx01 = gT[r0 + tP.y], gx02 = gT[r0 + tP.z], gx03 = gT[r0 + tP.w];
                const float gx10 = gT[r1 + tP.x], gx11 = gT[r1 + tP.y], gx12 = gT[r1 + tP.z], gx13 = gT[r1 + tP.w];
                const float gx20 = gT[r2 + tP.x], gx21 = gT[r2 + tP.y], gx22 = gT[r2 + tP.z], gx23 = gT[r2 + tP.w];
                const float gx30 = gT[r3 + tP.x], gx31 = gT[r3 + tP.y], gx32 = gT[r3 + tP.z], gx33 = gT[r3 + tP.w];
                const float gi10 = gT[r1 + tB.x];
                const float gi20 = gT[r2 + tB.x], gi21 = gT[r2 + tB.y];
                const float gi30 = gT[r3 + tB.x], gi31 = gT[r3 + tB.y], gi32 = gT[r3 + tB.z];
                // cross-block corrections (prev gammas; off-chain trees)
                const float gp0 = GP[p][0], gp1 = GP[p][1], gp2 = GP[p][2], gp3 = GP[p][3];
                const float w0  = RR[p][0] - (fmaf(gp1, gx01, gp0 * gx00) + fmaf(gp3, gx03, gp2 * gx02));
                const float w1b = RR[p][1] - (fmaf(gp1, gx11, gp0 * gx10) + fmaf(gp3, gx13, gp2 * gx12));
                const float w2b = RR[p][2] - (fmaf(gp1, gx21, gp0 * gx20) + fmaf(gp3, gx23, gp2 * gx22));
                const float w3b = RR[p][3] - (fmaf(gp1, gx31, gp0 * gx30) + fmaf(gp3, gx33, gp2 * gx32));
                // intra-block chain
                const float sc0 = scB, sc1 = scB - st, sc2 = scB - 2.f * st, sc3 = scB - 3.f * st;
                const float sw0 = sc0 * w0;                    const float g0 = C1 * sw0;
                const float w1  = fmaf(-g0, gi10, w1b);
                const float sw1 = sc1 * w1;                    const float g1 = C1 * sw1;
                const float w2  = fmaf(-g1, gi21, fmaf(-g0, gi20, w2b));
                const float sw2 = sc2 * w2;                    const float g2 = C1 * sw2;
                const float w3  = fmaf(-g2, gi32, fmaf(-g1, gi31, fmaf(-g0, gi30, w3b)));
                const float sw3 = sc3 * w3;                    const float g3 = C1 * sw3;
                GP[pq][0] = g0; GP[pq][1] = g1; GP[pq][2] = g2; GP[pq][3] = g3;
                scB -= 4.f * st;
                // S accumulation (register-sliced, predicated, off-chain)
                saccA += (tB.x == lane)  ? sw0 : 0.f;  saccB += (tB.x == laneB) ? sw0 : 0.f;
                saccA += (tB.y == lane)  ? sw1 : 0.f;  saccB += (tB.y == laneB) ? sw1 : 0.f;
                saccA += (tB.z == lane)  ? sw2 : 0.f;  saccB += (tB.z == laneB) ? sw2 : 0.f;
                saccA += (tB.w == lane)  ? sw3 : 0.f;  saccB += (tB.w == laneB) ? sw3 : 0.f;
                // partials for block B+1 on PRE-update u (keys of B+1 = K[pq])
                ull P0 = fma2(u1, K[pq][1], mul2(u0, K[pq][0]));
                ull P1 = fma2(u1, K[pq][3], mul2(u0, K[pq][2]));
                ull P2 = fma2(u1, K[pq][5], mul2(u0, K[pq][4]));
                ull P3 = fma2(u1, K[pq][7], mul2(u0, K[pq][6]));
                // rank-4 u update (keys of B = K[p])
                const ull g02 = pack2(-g0), g12 = pack2(-g1), g22 = pack2(-g2), g32 = pack2(-g3);
                u0 = fma2(g02, K[p][0], u0); u1 = fma2(g02, K[p][1], u1);
                u0 = fma2(g12, K[p][2], u0); u1 = fma2(g12, K[p][3], u1);
                u0 = fma2(g22, K[p][4], u0); u1 = fma2(g22, K[p][5], u1);
                u0 = fma2(g32, K[p][6], u0); u1 = fma2(g32, K[p][7], u1);
                // reduce partials -> raws for B+1
                {
                    float2 f = unpack2(P0); float r = f.x + f.y;
                    r += __shfl_xor_sync(0xffffffffu, r, 1);
                    r += __shfl_xor_sync(0xffffffffu, r, 2);
                    r += __shfl_xor_sync(0xffffffffu, r, 4);
                    RR[pq][0] = r;
                }
                {
                    float2 f = unpack2(P1); float r = f.x + f.y;
                    r += __shfl_xor_sync(0xffffffffu, r, 1);
                    r += __shfl_xor_sync(0xffffffffu, r, 2);
                    r += __shfl_xor_sync(0xffffffffu, r, 4);
                    RR[pq][1] = r;
                }
                {
                    float2 f = unpack2(P2); float r = f.x + f.y;
                    r += __shfl_xor_sync(0xffffffffu, r, 1);
                    r += __shfl_xor_sync(0xffffffffu, r, 2);
                    r += __shfl_xor_sync(0xffffffffu, r, 4);
                    RR[pq][2] = r;
                }
                {
                    float2 f = unpack2(P3); float r = f.x + f.y;
                    r += __shfl_xor_sync(0xffffffffu, r, 1);
                    r += __shfl_xor_sync(0xffffffffu, r, 2);
                    r += __shfl_xor_sync(0xffffffffu, r, 4);
                    RR[pq][3] = r;
                }
                // load keys of block B+2 into freed buffer K[p]
                {
                    const int4 tF = T[(kk + 2) & 3];
                    LD2(K[p][0], K[p][1], tF.x); LD2(K[p][2], K[p][3], tF.y);
                    LD2(K[p][4], K[p][5], tF.z); LD2(K[p][6], K[p][7], tF.w);
                }
            }
        }
        #undef LD2

        pS[lane]  = saccA;
        pS[laneB] = saccB;
    }
    __syncthreads();

    // ---- r[i] = sum_v S[v] * hhat[v, i]  (hhat pre-scaled by C1) ----
    if (tid < 64) {
        const bool ise = tid >= 32;
        const int i = tid & 31;
        const float* hT = ise ? s_he : s_hs;
        const float* Sv = s_S + (ise ? 64 : 0);
        float acc = 0.f;
        #pragma unroll 16
        for (int v = 0; v < V_; ++v) acc = fmaf(Sv[v], hT[(v << 5) + i], acc);
        s_r1[tid] = acc;
    }
    __syncthreads();

    // out = (r @ Wrp + brp) @ Wout + bout
    if (tid < H_) {
        float acc = brp[tid];
        #pragma unroll 16
        for (int k = 0; k < 2 * HALF_; ++k) acc = fmaf(s_r1[k], Wrp[k * H_ + tid], acc);
        s_tmp[tid] = acc;
    }
    __syncthreads();
    if (tid < V_) {
        float acc = bout[tid];
        #pragma unroll 16
        for (int d = 0; d < H_; ++d) acc = fmaf(s_tmp[d], Wout[d * V_ + tid], acc);
        out[b * V_ + tid] = acc;
    }
}

// ---------------------------------------------------------------------------
extern "C" void kernel_launch(void* const* d_in, const int* in_sizes, int n_in,
                              void* d_out, int out_size)
{
    const int*   seq   = (const int*)d_in[0];
    const float* embed = (const float*)d_in[1];
    const float* W1    = (const float*)d_in[2];
    const float* b1    = (const float*)d_in[3];
    const float* W2    = (const float*)d_in[4];
    const float* b2    = (const float*)d_in[5];
    const float* gamma = (const float*)d_in[6];
    const float* beta  = (const float*)d_in[7];
    const float* Ws    = (const float*)d_in[8];
    const float* bs    = (const float*)d_in[9];
    const float* We    = (const float*)d_in[10];
    const float* be    = (const float*)d_in[11];
    const float* Wrp   = (const float*)d_in[12];
    const float* brp   = (const float*)d_in[13];
    const float* Wout  = (const float*)d_in[14];
    const float* bout  = (const float*)d_in[15];
    float* out = (float*)d_out;

    static int smem_set = 0;
    const int smem_bytes = SMEM_FLOATS * 4 + 64;
    if (!smem_set) {
        cudaFuncSetAttribute(scan_kernel,
                             cudaFuncAttributeMaxDynamicSharedMemorySize, smem_bytes);
        smem_set = 1;
    }

    build_tables<<<V_, 128>>>(embed, W1, b1, W2, b2, gamma, beta, Ws, bs, We, be);
    build_gram<<<V_, V_>>>();
    scan_kernel<<<B_, NT_, smem_bytes>>>(seq, Wrp, brp, Wout, bout, out);
}

// round 16
// speedup vs baseline: 1.8008x; 1.0199x over previous
#include <cuda_runtime.h>

#define B_ 128
#define L_ 4096
#define H_ 64
#define V_ 64
#define HALF_ 32
#define C1 0.05f
#define LN_EPS 1e-5f
#define NT_ 256

typedef unsigned long long ull;

// Token-indexed tables (V=64): g_hs/g_he pre-scaled by (1-ALPHA)=C1.
__device__ float g_hs[V_ * HALF_];
__device__ float g_he[V_ * HALF_];
__device__ float g_ks[V_ * HALF_];
__device__ float g_ke[V_ * HALF_];
__device__ float g_Gs[V_ * V_];
__device__ float g_Ge[V_ * V_];

// ---------------- packed f32x2 helpers ----------------
__device__ __forceinline__ ull fma2(ull a, ull b, ull c) {
    ull d; asm("fma.rn.f32x2 %0,%1,%2,%3;" : "=l"(d) : "l"(a), "l"(b), "l"(c)); return d;
}
__device__ __forceinline__ ull mul2(ull a, ull b) {
    ull d; asm("mul.rn.f32x2 %0,%1,%2;" : "=l"(d) : "l"(a), "l"(b)); return d;
}
__device__ __forceinline__ ull pack2(float x) {
    ull d; asm("mov.b64 %0,{%1,%1};" : "=l"(d) : "f"(x)); return d;
}
__device__ __forceinline__ float2 unpack2(ull v) {
    float2 r; asm("mov.b64 {%0,%1},%2;" : "=f"(r.x), "=f"(r.y) : "l"(v)); return r;
}
// full 8-lane-slice reduce (3 bfly)
__device__ __forceinline__ float red8(ull P) {
    float2 f = unpack2(P);
    float r = f.x + f.y;
    r += __shfl_xor_sync(0xffffffffu, r, 1);
    r += __shfl_xor_sync(0xffffffffu, r, 2);
    r += __shfl_xor_sync(0xffffffffu, r, 4);
    return r;
}

// ---------------------------------------------------------------------------
// Kernel 1: per-token precompute. grid=64 (token), block=128.
// ---------------------------------------------------------------------------
__global__ void build_tables(const float* __restrict__ embed,
                             const float* __restrict__ W1, const float* __restrict__ b1,
                             const float* __restrict__ W2, const float* __restrict__ b2,
                             const float* __restrict__ gamma, const float* __restrict__ beta,
                             const float* __restrict__ Ws, const float* __restrict__ bs,
                             const float* __restrict__ We, const float* __restrict__ be)
{
    __shared__ float s_e[H_];
    __shared__ float s_a[2 * H_];
    __shared__ float s_x[H_];
    __shared__ float s_h[H_];
    __shared__ float s_mu, s_rstd;

    int tok = blockIdx.x;
    int tid = threadIdx.x;

    if (tid < H_) s_e[tid] = embed[tok * H_ + tid];
    __syncthreads();

    {
        float acc = b1[tid];
        #pragma unroll 32
        for (int h = 0; h < H_; ++h) acc = fmaf(s_e[h], __ldg(W1 + h * 2 * H_ + tid), acc);
        s_a[tid] = fmaxf(acc, 0.0f);
    }
    __syncthreads();

    if (tid < H_) {
        float acc = b2[tid];
        #pragma unroll 32
        for (int k = 0; k < 2 * H_; ++k) acc = fmaf(s_a[k], __ldg(W2 + k * H_ + tid), acc);
        s_x[tid] = s_e[tid] + acc;
    }
    __syncthreads();

    if (tid < 32) {
        float v = s_x[tid] + s_x[tid + 32];
        #pragma unroll
        for (int m = 16; m > 0; m >>= 1) v += __shfl_xor_sync(0xffffffffu, v, m);
        const float mu = v * (1.0f / H_);
        float d0 = s_x[tid] - mu, d1 = s_x[tid + 32] - mu;
        float vv = fmaf(d0, d0, d1 * d1);
        #pragma unroll
        for (int m = 16; m > 0; m >>= 1) vv += __shfl_xor_sync(0xffffffffu, vv, m);
        if (tid == 0) {
            s_mu = mu;
            s_rstd = rsqrtf(vv * (1.0f / H_) + LN_EPS);
        }
    }
    __syncthreads();

    if (tid < H_) s_h[tid] = (s_x[tid] - s_mu) * s_rstd * gamma[tid] + beta[tid];
    __syncthreads();

    int wid = tid >> 5, lane = tid & 31;
    if (wid == 0) {
        float acc = bs[lane];
        #pragma unroll 32
        for (int j = 0; j < H_; ++j) acc = fmaf(s_h[j], __ldg(Ws + j * HALF_ + lane), acc);
        float ss = acc * acc;
        #pragma unroll
        for (int m = 16; m > 0; m >>= 1) ss += __shfl_xor_sync(0xffffffffu, ss, m);
        float n = fmaxf(sqrtf(ss), 1e-12f);
        g_hs[tok * HALF_ + lane] = C1 * acc;
        g_ks[tok * HALF_ + lane] = acc / n;
    } else if (wid == 1) {
        float acc = be[lane];
        #pragma unroll 32
        for (int j = 0; j < H_; ++j) acc = fmaf(s_h[j], __ldg(We + j * HALF_ + lane), acc);
        float ss = acc * acc;
        #pragma unroll
        for (int m = 16; m > 0; m >>= 1) ss += __shfl_xor_sync(0xffffffffu, ss, m);
        float n = fmaxf(sqrtf(ss), 1e-12f);
        g_he[tok * HALF_ + lane] = C1 * acc;
        g_ke[tok * HALF_ + lane] = acc / n;
    }
}

// ---------------------------------------------------------------------------
// Kernel 1b: 64x64 key Gram matrices. grid=64, block=64.
// ---------------------------------------------------------------------------
__global__ void build_gram()
{
    int a = blockIdx.x;
    int b = threadIdx.x;
    float ss = 0.f, se = 0.f;
    #pragma unroll
    for (int j = 0; j < HALF_; ++j) {
        ss = fmaf(g_ks[a * HALF_ + j], g_ks[b * HALF_ + j], ss);
        se = fmaf(g_ke[a * HALF_ + j], g_ke[b * HALF_ + j], se);
    }
    g_Gs[a * V_ + b] = ss;
    g_Ge[a * V_ + b] = se;
}

// ---- smem layout (float offsets); keys/Gram have 65th zero row (pad token 64)
#define OFF_KS   0
#define OFF_KE   2080
#define OFF_HS   4160
#define OFF_HE   6208
#define OFF_GS   8256
#define OFF_GE   12416
#define OFF_REV  16576      /* 4112 ints, 16B aligned */
#define OFF_S    20688
#define OFF_R1   20816
#define OFF_TMP  20880
#define OFF_QTOK 20944
#define SMEM_FLOATS 20948

// ---------------------------------------------------------------------------
// Kernel 2: rank-4 blocked backward-vector pass, reduce OFF the carried path.
//   Partials for block n+2 issued at block n AFTER the rank-4 update (on
//   u_{n+1}); reduced during block n+1 (full block of slack); consumed at
//   block n+2 with the SAME corrections as R15 (16 cross-Gram terms with the
//   previous block's gammas + intra-block chain).
//   Carried chain per block: correction tree + intra chain only (~57 cyc).
// 2 scan warps (w0=s SMSP0, w1=e SMSP1); u sliced 4 floats/lane (8 slices).
// Rings: keys K[4] (blocks n..n+3), tokens Tn[8], partials/RR ping-pong.
// Inner unroll 8 -> all ring indices compile-time. 128 x 8 = 1024 blocks.
// ---------------------------------------------------------------------------
__global__ __launch_bounds__(NT_, 1)
void scan_kernel(const int* __restrict__ seq,
                 const float* __restrict__ Wrp, const float* __restrict__ brp,
                 const float* __restrict__ Wout, const float* __restrict__ bout,
                 float* __restrict__ out)
{
    extern __shared__ float sm[];
    float* s_ks = sm + OFF_KS;
    float* s_ke = sm + OFF_KE;
    float* s_hs = sm + OFF_HS;
    float* s_he = sm + OFF_HE;
    float* s_Gs = sm + OFF_GS;
    float* s_Ge = sm + OFF_GE;
    int*   s_rev = (int*)(sm + OFF_REV);
    float* s_S   = sm + OFF_S;
    float* s_r1  = sm + OFF_R1;
    float* s_tmp = sm + OFF_TMP;
    int*   s_qtok = (int*)(sm + OFF_QTOK);

    const int b = blockIdx.x;
    const int tid = threadIdx.x;
    const int wid = tid >> 5;
    const int lane = tid & 31;

    // ---- stage reversed sequence + tables (65-row keys / Gram, zero row) ----
    {
        const int* seqb = seq + b * L_;
        for (int i = tid; i <= L_ - 2; i += NT_) s_rev[i] = seqb[L_ - 2 - i];
        if (tid < 17) s_rev[(L_ - 1) + tid] = 64;          // pad tokens
        if (tid == 0) *s_qtok = seqb[L_ - 1];
    }
    for (int k = tid; k < V_ * HALF_; k += NT_) {
        s_ks[k] = g_ks[k];
        s_ke[k] = g_ke[k];
        s_hs[k] = g_hs[k];
        s_he[k] = g_he[k];
    }
    if (tid < 32) { s_ks[2048 + tid] = 0.f; s_ke[2048 + tid] = 0.f; }
    for (int k = tid; k < V_ * V_; k += NT_) {
        s_Gs[k] = g_Gs[k];
        s_Ge[k] = g_Ge[k];
    }
    if (tid < 64) { s_Gs[4096 + tid] = 0.f; s_Ge[4096 + tid] = 0.f; }
    __syncthreads();

    if (wid < 2) {
        const bool is_e = (wid == 1);
        const float* kT = is_e ? s_ke : s_ks;
        const float* gT = is_e ? s_Ge : s_Gs;
        float* pS = s_S + (is_e ? 64 : 0);
        const int col0 = (lane & 7) << 2;        // 4-float slice
        const int laneB = lane + 32;
        const float invL = 1.0f / (float)L_;
        const float st = is_e ? invL : 0.0f;
        float scB = is_e ? (float)(L_ - 1) * invL : 1.0f;
        float saccA = 0.f, saccB = 0.f;

        ull K[4][8];         // key ring: block m -> K[m&3] (4 tokens x 2 ull)
        int4 Tn[8];          // token ring: block m -> Tn[m&7]
        ull PP[2][4];        // collapsed partials ping-pong
        float RRb[2][4];     // reduced raws ping-pong
        float GPr[4];        // previous block gammas
        ull u0, u1;

        #define LD2(DST0, DST1, TOK) { \
            const ulonglong2 v_ = *(const ulonglong2*)(kT + ((TOK) << 5) + col0); \
            DST0 = v_.x; DST1 = v_.y; }

        // ---- prologue ----
        {
            const int tq = *s_qtok;
            LD2(u0, u1, tq);                          // u = q
        }
        Tn[0] = *(const int4*)(s_rev + 0);
        Tn[1] = *(const int4*)(s_rev + 4);
        Tn[2] = *(const int4*)(s_rev + 8);
        Tn[3] = *(const int4*)(s_rev + 12);
        Tn[4] = *(const int4*)(s_rev + 16);
        Tn[5] = make_int4(64, 64, 64, 64);
        Tn[6] = make_int4(64, 64, 64, 64);
        Tn[7] = make_int4(0, 0, 0, 0);               // dummy prev-block tokens
        LD2(K[0][0], K[0][1], Tn[0].x); LD2(K[0][2], K[0][3], Tn[0].y);
        LD2(K[0][4], K[0][5], Tn[0].z); LD2(K[0][6], K[0][7], Tn[0].w);
        LD2(K[1][0], K[1][1], Tn[1].x); LD2(K[1][2], K[1][3], Tn[1].y);
        LD2(K[1][4], K[1][5], Tn[1].z); LD2(K[1][6], K[1][7], Tn[1].w);
        LD2(K[2][0], K[2][1], Tn[2].x); LD2(K[2][2], K[2][3], Tn[2].y);
        LD2(K[2][4], K[2][5], Tn[2].z); LD2(K[2][6], K[2][7], Tn[2].w);
        // RRb[0] = reduced k(block0).q ; PP[1] = collapsed partials k(block1).q
        #pragma unroll
        for (int i = 0; i < 4; ++i) {
            RRb[0][i] = red8(fma2(u1, K[0][2 * i + 1], mul2(u0, K[0][2 * i])));
            PP[1][i]  = fma2(u1, K[1][2 * i + 1], mul2(u0, K[1][2 * i]));
            RRb[1][i] = 0.f;
        }
        GPr[0] = 0.f; GPr[1] = 0.f; GPr[2] = 0.f; GPr[3] = 0.f;

        // ---- main: 128 outer x 8 blocks ----
        #pragma unroll 1
        for (int outer = 0; outer < 128; ++outer) {
            const int base4 = outer << 5;       // token index of block 8*outer
            #pragma unroll
            for (int kk = 0; kk < 8; ++kk) {
                const int4 tB = Tn[kk & 7];
                const int4 tP = Tn[(kk + 7) & 7];
                // token prefetch, block n+4
                Tn[(kk + 4) & 7] = *(const int4*)(s_rev + base4 + ((kk + 4) << 2));
                // Gram loads for corrections (block n vs n-1) + intra
                const int r0 = tB.x << 6, r1 = tB.y << 6, r2 = tB.z << 6, r3 = tB.w << 6;
                const float gx00 = gT[r0 + tP.x], gx01 = gT[r0 + tP.y], gx02 = gT[r0 + tP.z], gx03 = gT[r0 + tP.w];
                const float gx10 = gT[r1 + tP.x], gx11 = gT[r1 + tP.y], gx12 = gT[r1 + tP.z], gx13 = gT[r1 + tP.w];
                const float gx20 = gT[r2 + tP.x], gx21 = gT[r2 + tP.y], gx22 = gT[r2 + tP.z], gx23 = gT[r2 + tP.w];
                const float gx30 = gT[r3 + tP.x], gx31 = gT[r3 + tP.y], gx32 = gT[r3 + tP.z], gx33 = gT[r3 + tP.w];
                const float gi10 = gT[r1 + tB.x];
                const float gi20 = gT[r2 + tB.x], gi21 = gT[r2 + tB.y];
                const float gi30 = gT[r3 + tB.x], gi31 = gT[r3 + tB.y], gi32 = gT[r3 + tB.z];
                // cross-block corrections (prev gammas)
                const float gp0 = GPr[0], gp1 = GPr[1], gp2 = GPr[2], gp3 = GPr[3];
                const float w0  = RRb[kk & 1][0] - (fmaf(gp1, gx01, gp0 * gx00) + fmaf(gp3, gx03, gp2 * gx02));
                const float w1b = RRb[kk & 1][1] - (fmaf(gp1, gx11, gp0 * gx10) + fmaf(gp3, gx13, gp2 * gx12));
                const float w2b = RRb[kk & 1][2] - (fmaf(gp1, gx21, gp0 * gx20) + fmaf(gp3, gx23, gp2 * gx22));
                const float w3b = RRb[kk & 1][3] - (fmaf(gp1, gx31, gp0 * gx30) + fmaf(gp3, gx33, gp2 * gx32));
                // intra-block chain
                const float sc0 = scB, sc1 = scB - st, sc2 = scB - 2.f * st, sc3 = scB - 3.f * st;
                const float sw0 = sc0 * w0;                    const float g0 = C1 * sw0;
                const float w1  = fmaf(-g0, gi10, w1b);
                const float sw1 = sc1 * w1;                    const float g1 = C1 * sw1;
                const float w2  = fmaf(-g1, gi21, fmaf(-g0, gi20, w2b));
                const float sw2 = sc2 * w2;                    const float g2 = C1 * sw2;
                const float w3  = fmaf(-g2, gi32, fmaf(-g1, gi31, fmaf(-g0, gi30, w3b)));
                const float sw3 = sc3 * w3;                    const float g3 = C1 * sw3;
                GPr[0] = g0; GPr[1] = g1; GPr[2] = g2; GPr[3] = g3;
                scB -= 4.f * st;
                // S accumulation (register-sliced, predicated, off-chain)
                saccA += (tB.x == lane)  ? sw0 : 0.f;  saccB += (tB.x == laneB) ? sw0 : 0.f;
                saccA += (tB.y == lane)  ? sw1 : 0.f;  saccB += (tB.y == laneB) ? sw1 : 0.f;
                saccA += (tB.z == lane)  ? sw2 : 0.f;  saccB += (tB.z == laneB) ? sw2 : 0.f;
                saccA += (tB.w == lane)  ? sw3 : 0.f;  saccB += (tB.w == laneB) ? sw3 : 0.f;
                // rank-4 u update (keys of block n)
                {
                    const ull g02 = pack2(-g0), g12 = pack2(-g1), g22 = pack2(-g2), g32 = pack2(-g3);
                    u0 = fma2(g02, K[kk & 3][0], u0); u1 = fma2(g02, K[kk & 3][1], u1);
                    u0 = fma2(g12, K[kk & 3][2], u0); u1 = fma2(g12, K[kk & 3][3], u1);
                    u0 = fma2(g22, K[kk & 3][4], u0); u1 = fma2(g22, K[kk & 3][5], u1);
                    u0 = fma2(g32, K[kk & 3][6], u0); u1 = fma2(g32, K[kk & 3][7], u1);
                }
                // partials for block n+2 on POST-update u (keys of block n+2)
                PP[kk & 1][0] = fma2(u1, K[(kk + 2) & 3][1], mul2(u0, K[(kk + 2) & 3][0]));
                PP[kk & 1][1] = fma2(u1, K[(kk + 2) & 3][3], mul2(u0, K[(kk + 2) & 3][2]));
                PP[kk & 1][2] = fma2(u1, K[(kk + 2) & 3][5], mul2(u0, K[(kk + 2) & 3][4]));
                PP[kk & 1][3] = fma2(u1, K[(kk + 2) & 3][7], mul2(u0, K[(kk + 2) & 3][6]));
                // reduce partials issued last block (target block n+1) — slack
                RRb[(kk + 1) & 1][0] = red8(PP[(kk + 1) & 1][0]);
                RRb[(kk + 1) & 1][1] = red8(PP[(kk + 1) & 1][1]);
                RRb[(kk + 1) & 1][2] = red8(PP[(kk + 1) & 1][2]);
                RRb[(kk + 1) & 1][3] = red8(PP[(kk + 1) & 1][3]);
                // load keys of block n+3 into freed ring slot
                {
                    const int4 tF = Tn[(kk + 3) & 7];
                    LD2(K[(kk + 3) & 3][0], K[(kk + 3) & 3][1], tF.x);
                    LD2(K[(kk + 3) & 3][2], K[(kk + 3) & 3][3], tF.y);
                    LD2(K[(kk + 3) & 3][4], K[(kk + 3) & 3][5], tF.z);
                    LD2(K[(kk + 3) & 3][6], K[(kk + 3) & 3][7], tF.w);
                }
            }
        }
        #undef LD2

        pS[lane]  = saccA;
        pS[laneB] = saccB;
    }
    __syncthreads();

    // ---- r[i] = sum_v S[v] * hhat[v, i]  (hhat pre-scaled by C1) ----
    if (tid < 64) {
        const bool ise = tid >= 32;
        const int i = tid & 31;
        const float* hT = ise ? s_he : s_hs;
        const float* Sv = s_S + (ise ? 64 : 0);
        float acc = 0.f;
        #pragma unroll 16
        for (int v = 0; v < V_; ++v) acc = fmaf(Sv[v], hT[(v << 5) + i], acc);
        s_r1[tid] = acc;
    }
    __syncthreads();

    // out = (r @ Wrp + brp) @ Wout + bout
    if (tid < H_) {
        float acc = brp[tid];
        #pragma unroll 16
        for (int k = 0; k < 2 * HALF_; ++k) acc = fmaf(s_r1[k], Wrp[k * H_ + tid], acc);
        s_tmp[tid] = acc;
    }
    __syncthreads();
    if (tid < V_) {
        float acc = bout[tid];
        #pragma unroll 16
        for (int d = 0; d < H_; ++d) acc = fmaf(s_tmp[d], Wout[d * V_ + tid], acc);
        out[b * V_ + tid] = acc;
    }
}

// ---------------------------------------------------------------------------
extern "C" void kernel_launch(void* const* d_in, const int* in_sizes, int n_in,
                              void* d_out, int out_size)
{
    const int*   seq   = (const int*)d_in[0];
    const float* embed = (const float*)d_in[1];
    const float* W1    = (const float*)d_in[2];
    const float* b1    = (const float*)d_in[3];
    const float* W2    = (const float*)d_in[4];
    const float* b2    = (const float*)d_in[5];
    const float* gamma = (const float*)d_in[6];
    const float* beta  = (const float*)d_in[7];
    const float* Ws    = (const float*)d_in[8];
    const float* bs    = (const float*)d_in[9];
    const float* We    = (const float*)d_in[10];
    const float* be    = (const float*)d_in[11];
    const float* Wrp   = (const float*)d_in[12];
    const float* brp   = (const float*)d_in[13];
    const float* Wout  = (const float*)d_in[14];
    const float* bout  = (const float*)d_in[15];
    float* out = (float*)d_out;

    static int smem_set = 0;
    const int smem_bytes = SMEM_FLOATS * 4 + 64;
    if (!smem_set) {
        cudaFuncSetAttribute(scan_kernel,
                             cudaFuncAttributeMaxDynamicSharedMemorySize, smem_bytes);
        smem_set = 1;
    }

    build_tables<<<V_, 128>>>(embed, W1, b1, W2, b2, gamma, beta, Ws, bs, We, be);
    build_gram<<<V_, V_>>>();
    scan_kernel<<<B_, NT_, smem_bytes>>>(seq, Wrp, brp, Wout, bout, out);
}

// round 17
// speedup vs baseline: 2.0924x; 1.1619x over previous
#include <cuda_runtime.h>

#define B_ 128
#define L_ 4096
#define H_ 64
#define V_ 64
#define HALF_ 32
#define C1 0.05f
#define LN_EPS 1e-5f
#define NT_ 256

typedef unsigned long long ull;

// Token-indexed tables (V=64): g_hs/g_he pre-scaled by (1-ALPHA)=C1.
__device__ float g_hs[V_ * HALF_];
__device__ float g_he[V_ * HALF_];
__device__ float g_ks[V_ * HALF_];
__device__ float g_ke[V_ * HALF_];

// ---------------- packed f32x2 helpers ----------------
__device__ __forceinline__ ull fma2(ull a, ull b, ull c) {
    ull d; asm("fma.rn.f32x2 %0,%1,%2,%3;" : "=l"(d) : "l"(a), "l"(b), "l"(c)); return d;
}
__device__ __forceinline__ ull mul2(ull a, ull b) {
    ull d; asm("mul.rn.f32x2 %0,%1,%2;" : "=l"(d) : "l"(a), "l"(b)); return d;
}
__device__ __forceinline__ ull pack2(float x) {
    ull d; asm("mov.b64 %0,{%1,%1};" : "=l"(d) : "f"(x)); return d;
}
__device__ __forceinline__ float2 unpack2(ull v) {
    float2 r; asm("mov.b64 {%0,%1},%2;" : "=f"(r.x), "=f"(r.y) : "l"(v)); return r;
}
// group-local all-reduce over the 8 lanes of each lane-group (xor 1,2,4)
__device__ __forceinline__ float red_grp(ull P) {
    float2 f = unpack2(P);
    float r = f.x + f.y;
    r += __shfl_xor_sync(0xffffffffu, r, 1);
    r += __shfl_xor_sync(0xffffffffu, r, 2);
    r += __shfl_xor_sync(0xffffffffu, r, 4);
    return r;
}

// ---------------------------------------------------------------------------
// Kernel 1: per-token precompute. grid=64 (token), block=128.
// ---------------------------------------------------------------------------
__global__ void build_tables(const float* __restrict__ embed,
                             const float* __restrict__ W1, const float* __restrict__ b1,
                             const float* __restrict__ W2, const float* __restrict__ b2,
                             const float* __restrict__ gamma, const float* __restrict__ beta,
                             const float* __restrict__ Ws, const float* __restrict__ bs,
                             const float* __restrict__ We, const float* __restrict__ be)
{
    __shared__ float s_e[H_];
    __shared__ float s_a[2 * H_];
    __shared__ float s_x[H_];
    __shared__ float s_h[H_];
    __shared__ float s_mu, s_rstd;

    int tok = blockIdx.x;
    int tid = threadIdx.x;

    if (tid < H_) s_e[tid] = embed[tok * H_ + tid];
    __syncthreads();

    {
        float acc = b1[tid];
        #pragma unroll 32
        for (int h = 0; h < H_; ++h) acc = fmaf(s_e[h], __ldg(W1 + h * 2 * H_ + tid), acc);
        s_a[tid] = fmaxf(acc, 0.0f);
    }
    __syncthreads();

    if (tid < H_) {
        float acc = b2[tid];
        #pragma unroll 32
        for (int k = 0; k < 2 * H_; ++k) acc = fmaf(s_a[k], __ldg(W2 + k * H_ + tid), acc);
        s_x[tid] = s_e[tid] + acc;
    }
    __syncthreads();

    if (tid < 32) {
        float v = s_x[tid] + s_x[tid + 32];
        #pragma unroll
        for (int m = 16; m > 0; m >>= 1) v += __shfl_xor_sync(0xffffffffu, v, m);
        const float mu = v * (1.0f / H_);
        float d0 = s_x[tid] - mu, d1 = s_x[tid + 32] - mu;
        float vv = fmaf(d0, d0, d1 * d1);
        #pragma unroll
        for (int m = 16; m > 0; m >>= 1) vv += __shfl_xor_sync(0xffffffffu, vv, m);
        if (tid == 0) {
            s_mu = mu;
            s_rstd = rsqrtf(vv * (1.0f / H_) + LN_EPS);
        }
    }
    __syncthreads();

    if (tid < H_) s_h[tid] = (s_x[tid] - s_mu) * s_rstd * gamma[tid] + beta[tid];
    __syncthreads();

    int wid = tid >> 5, lane = tid & 31;
    if (wid == 0) {
        float acc = bs[lane];
        #pragma unroll 32
        for (int j = 0; j < H_; ++j) acc = fmaf(s_h[j], __ldg(Ws + j * HALF_ + lane), acc);
        float ss = acc * acc;
        #pragma unroll
        for (int m = 16; m > 0; m >>= 1) ss += __shfl_xor_sync(0xffffffffu, ss, m);
        float n = fmaxf(sqrtf(ss), 1e-12f);
        g_hs[tok * HALF_ + lane] = C1 * acc;
        g_ks[tok * HALF_ + lane] = acc / n;
    } else if (wid == 1) {
        float acc = be[lane];
        #pragma unroll 32
        for (int j = 0; j < H_; ++j) acc = fmaf(s_h[j], __ldg(We + j * HALF_ + lane), acc);
        float ss = acc * acc;
        #pragma unroll
        for (int m = 16; m > 0; m >>= 1) ss += __shfl_xor_sync(0xffffffffu, ss, m);
        float n = fmaxf(sqrtf(ss), 1e-12f);
        g_he[tok * HALF_ + lane] = C1 * acc;
        g_ke[tok * HALF_ + lane] = acc / n;
    }
}

// ---- smem layout (float offsets); keys/Gram have 65th zero row (pad token 64)
#define OFF_KS   0
#define OFF_KE   2080
#define OFF_HS   4160
#define OFF_HE   6208
#define OFF_GS   8256
#define OFF_GE   12416
#define OFF_REV  16576      /* 4112 ints, 16B aligned */
#define OFF_S    20688
#define OFF_R1   20816
#define OFF_TMP  20880
#define OFF_QTOK 20944
#define SMEM_FLOATS 20948

// ---------------------------------------------------------------------------
// Kernel 2: rank-4 blocked backward-vector pass, group-sliced dots.
//   r = M_{L-1} q = sum_t sc_t w_t hhat_t;  w_t = k_t . u_{t+1};
//   u_t = u_{t+1} - C1*sc_t*w_t k_t;  u_{L-1} = q.
// Lane-group g = lane>>3 computes ONLY dot g of each 4-token block; one
// 3-bfly all-reduce reduces all 4 dots simultaneously; consumption broadcasts
// via 4 shfl.idx. Partials for block n+2 issued at n post-update (u_{n+1});
// reduced at n+1; consumed at n+2 with 16 cross-Gram corrections (prev
// gammas) + intra-block chain — identical semantics to R16.
// Gram tables computed in-CTA (2-launch pattern). 2 scan warps (s, e).
// ---------------------------------------------------------------------------
__global__ __launch_bounds__(NT_, 1)
void scan_kernel(const int* __restrict__ seq,
                 const float* __restrict__ Wrp, const float* __restrict__ brp,
                 const float* __restrict__ Wout, const float* __restrict__ bout,
                 float* __restrict__ out)
{
    extern __shared__ float sm[];
    float* s_ks = sm + OFF_KS;
    float* s_ke = sm + OFF_KE;
    float* s_hs = sm + OFF_HS;
    float* s_he = sm + OFF_HE;
    float* s_Gs = sm + OFF_GS;
    float* s_Ge = sm + OFF_GE;
    int*   s_rev = (int*)(sm + OFF_REV);
    float* s_S   = sm + OFF_S;
    float* s_r1  = sm + OFF_R1;
    float* s_tmp = sm + OFF_TMP;
    int*   s_qtok = (int*)(sm + OFF_QTOK);

    const int b = blockIdx.x;
    const int tid = threadIdx.x;
    const int wid = tid >> 5;
    const int lane = tid & 31;

    // ---- stage reversed sequence + tables ----
    {
        const int* seqb = seq + b * L_;
        for (int i = tid; i <= L_ - 2; i += NT_) s_rev[i] = seqb[L_ - 2 - i];
        if (tid < 17) s_rev[(L_ - 1) + tid] = 64;          // pad tokens
        if (tid == 0) *s_qtok = seqb[L_ - 1];
    }
    for (int k = tid; k < V_ * HALF_; k += NT_) {
        s_ks[k] = g_ks[k];
        s_ke[k] = g_ke[k];
        s_hs[k] = g_hs[k];
        s_he[k] = g_he[k];
    }
    if (tid < 32) { s_ks[2048 + tid] = 0.f; s_ke[2048 + tid] = 0.f; }
    __syncthreads();

    // ---- Gram tables in-CTA (symmetric) + zero pad row ----
    for (int idx = tid; idx < V_ * V_; idx += NT_) {
        const int a = idx >> 6, c = idx & 63;
        float ss = 0.f, se = 0.f;
        #pragma unroll
        for (int j = 0; j < HALF_; ++j) {
            ss = fmaf(s_ks[(a << 5) + j], s_ks[(c << 5) + j], ss);
            se = fmaf(s_ke[(a << 5) + j], s_ke[(c << 5) + j], se);
        }
        s_Gs[idx] = ss;
        s_Ge[idx] = se;
    }
    if (tid < 64) { s_Gs[4096 + tid] = 0.f; s_Ge[4096 + tid] = 0.f; }
    __syncthreads();

    if (wid < 2) {
        const bool is_e = (wid == 1);
        const float* kT = is_e ? s_ke : s_ks;
        const float* gT = is_e ? s_Ge : s_Gs;
        float* pS = s_S + (is_e ? 64 : 0);
        const int grp = lane >> 3;
        const int col0 = (lane & 7) << 2;        // 4-float slice
        const int laneB = lane + 32;
        const float invL = 1.0f / (float)L_;
        const float st = is_e ? invL : 0.0f;
        float scB = is_e ? (float)(L_ - 1) * invL : 1.0f;
        float saccA = 0.f, saccB = 0.f;

        ull K[2][8];         // update keys ping-pong (4 tokens x 2 ull)
        ull PK[2][2];        // per-group partial keys ping-pong
        ull PP[2];           // collapsed partials ping-pong (1 per block)
        float RR[2];         // reduced dots (group-distributed) ping-pong
        float GPr0 = 0.f, GPr1 = 0.f, GPr2 = 0.f, GPr3 = 0.f;
        int4 Tn[8];
        ull u0, u1;

        #define LD2(DST0, DST1, TOK) { \
            const ulonglong2 v_ = *(const ulonglong2*)(kT + ((TOK) << 5) + col0); \
            DST0 = v_.x; DST1 = v_.y; }

        // ---- prologue ----
        LD2(u0, u1, *s_qtok);                        // u = q
        Tn[0] = *(const int4*)(s_rev + 0);
        Tn[1] = *(const int4*)(s_rev + 4);
        Tn[2] = *(const int4*)(s_rev + 8);
        Tn[3] = *(const int4*)(s_rev + 12);
        Tn[4] = *(const int4*)(s_rev + 16);
        Tn[5] = make_int4(64, 64, 64, 64);
        Tn[6] = make_int4(64, 64, 64, 64);
        Tn[7] = make_int4(0, 0, 0, 0);               // dummy prev-block tokens
        // K[0] = keys(block0)
        LD2(K[0][0], K[0][1], Tn[0].x); LD2(K[0][2], K[0][3], Tn[0].y);
        LD2(K[0][4], K[0][5], Tn[0].z); LD2(K[0][6], K[0][7], Tn[0].w);
        // PK[0] = per-group key of block2 (partials at block0 target block2)
        { const int pt = s_rev[8 + grp];  LD2(PK[0][0], PK[0][1], pt); }
        // PP[1] = per-group partials of block1 on q (reduced at block0)
        { const int pt = s_rev[4 + grp];
          ull a0, a1; LD2(a0, a1, pt);
          PP[1] = fma2(u1, a1, mul2(u0, a0)); }
        // RR[0] = exact dots of block0 on q (group-distributed)
        { const int pt = s_rev[0 + grp];
          ull a0, a1; LD2(a0, a1, pt);
          RR[0] = red_grp(fma2(u1, a1, mul2(u0, a0))); }
        RR[1] = 0.f;

        // ---- main: 128 outer x 8 blocks (1024 blocks, 4095 real + 1 pad) ----
        #pragma unroll 1
        for (int outer = 0; outer < 128; ++outer) {
            const int base4 = outer << 5;
            #pragma unroll
            for (int kk = 0; kk < 8; ++kk) {
                const int4 tB = Tn[kk & 7];
                const int4 tP = Tn[(kk + 7) & 7];
                // token prefetch, block n+4
                Tn[(kk + 4) & 7] = *(const int4*)(s_rev + base4 + ((kk + 4) << 2));
                // broadcast consumed dots (group g's value lives in lanes 8g..8g+7)
                const float RRc = RR[kk & 1];
                const float rb0 = __shfl_sync(0xffffffffu, RRc, 0);
                const float rb1 = __shfl_sync(0xffffffffu, RRc, 8);
                const float rb2 = __shfl_sync(0xffffffffu, RRc, 16);
                const float rb3 = __shfl_sync(0xffffffffu, RRc, 24);
                // Gram loads
                const int r0 = tB.x << 6, r1 = tB.y << 6, r2 = tB.z << 6, r3 = tB.w << 6;
                const float gx00 = gT[r0 + tP.x], gx01 = gT[r0 + tP.y], gx02 = gT[r0 + tP.z], gx03 = gT[r0 + tP.w];
                const float gx10 = gT[r1 + tP.x], gx11 = gT[r1 + tP.y], gx12 = gT[r1 + tP.z], gx13 = gT[r1 + tP.w];
                const float gx20 = gT[r2 + tP.x], gx21 = gT[r2 + tP.y], gx22 = gT[r2 + tP.z], gx23 = gT[r2 + tP.w];
                const float gx30 = gT[r3 + tP.x], gx31 = gT[r3 + tP.y], gx32 = gT[r3 + tP.z], gx33 = gT[r3 + tP.w];
                const float gi10 = gT[r1 + tB.x];
                const float gi20 = gT[r2 + tB.x], gi21 = gT[r2 + tB.y];
                const float gi30 = gT[r3 + tB.x], gi31 = gT[r3 + tB.y], gi32 = gT[r3 + tB.z];
                // cross-block corrections (prev gammas)
                const float w0  = rb0 - (fmaf(GPr1, gx01, GPr0 * gx00) + fmaf(GPr3, gx03, GPr2 * gx02));
                const float w1b = rb1 - (fmaf(GPr1, gx11, GPr0 * gx10) + fmaf(GPr3, gx13, GPr2 * gx12));
                const float w2b = rb2 - (fmaf(GPr1, gx21, GPr0 * gx20) + fmaf(GPr3, gx23, GPr2 * gx22));
                const float w3b = rb3 - (fmaf(GPr1, gx31, GPr0 * gx30) + fmaf(GPr3, gx33, GPr2 * gx32));
                // intra-block chain
                const float sc0 = scB, sc1 = scB - st, sc2 = scB - 2.f * st, sc3 = scB - 3.f * st;
                const float sw0 = sc0 * w0;                    const float g0 = C1 * sw0;
                const float w1  = fmaf(-g0, gi10, w1b);
                const float sw1 = sc1 * w1;                    const float g1 = C1 * sw1;
                const float w2  = fmaf(-g1, gi21, fmaf(-g0, gi20, w2b));
                const float sw2 = sc2 * w2;                    const float g2 = C1 * sw2;
                const float w3  = fmaf(-g2, gi32, fmaf(-g1, gi31, fmaf(-g0, gi30, w3b)));
                const float sw3 = sc3 * w3;                    const float g3 = C1 * sw3;
                GPr0 = g0; GPr1 = g1; GPr2 = g2; GPr3 = g3;
                scB -= 4.f * st;
                // S accumulation (register-sliced, predicated, off-chain)
                saccA += (tB.x == lane)  ? sw0 : 0.f;  saccB += (tB.x == laneB) ? sw0 : 0.f;
                saccA += (tB.y == lane)  ? sw1 : 0.f;  saccB += (tB.y == laneB) ? sw1 : 0.f;
                saccA += (tB.z == lane)  ? sw2 : 0.f;  saccB += (tB.z == laneB) ? sw2 : 0.f;
                saccA += (tB.w == lane)  ? sw3 : 0.f;  saccB += (tB.w == laneB) ? sw3 : 0.f;
                // rank-4 u update (keys of block n)
                {
                    const ull g02 = pack2(-g0), g12 = pack2(-g1), g22 = pack2(-g2), g32 = pack2(-g3);
                    u0 = fma2(g02, K[kk & 1][0], u0); u1 = fma2(g02, K[kk & 1][1], u1);
                    u0 = fma2(g12, K[kk & 1][2], u0); u1 = fma2(g12, K[kk & 1][3], u1);
                    u0 = fma2(g22, K[kk & 1][4], u0); u1 = fma2(g22, K[kk & 1][5], u1);
                    u0 = fma2(g32, K[kk & 1][6], u0); u1 = fma2(g32, K[kk & 1][7], u1);
                }
                // per-group partial for block n+2 on POST-update u
                PP[kk & 1] = fma2(u1, PK[kk & 1][1], mul2(u0, PK[kk & 1][0]));
                // reduce partials issued last block (target block n+1) — slack
                RR[(kk + 1) & 1] = red_grp(PP[(kk + 1) & 1]);
                // load per-group partial key for block n+3
                { const int pt = s_rev[base4 + ((kk + 3) << 2) + grp];
                  LD2(PK[(kk + 1) & 1][0], PK[(kk + 1) & 1][1], pt); }
                // load update keys of block n+1
                {
                    const int4 tN = Tn[(kk + 1) & 7];
                    LD2(K[(kk + 1) & 1][0], K[(kk + 1) & 1][1], tN.x);
                    LD2(K[(kk + 1) & 1][2], K[(kk + 1) & 1][3], tN.y);
                    LD2(K[(kk + 1) & 1][4], K[(kk + 1) & 1][5], tN.z);
                    LD2(K[(kk + 1) & 1][6], K[(kk + 1) & 1][7], tN.w);
                }
            }
        }
        #undef LD2

        pS[lane]  = saccA;
        pS[laneB] = saccB;
    }
    __syncthreads();

    // ---- r[i] = sum_v S[v] * hhat[v, i]  (hhat pre-scaled by C1) ----
    if (tid < 64) {
        const bool ise = tid >= 32;
        const int i = tid & 31;
        const float* hT = ise ? s_he : s_hs;
        const float* Sv = s_S + (ise ? 64 : 0);
        float acc = 0.f;
        #pragma unroll 16
        for (int v = 0; v < V_; ++v) acc = fmaf(Sv[v], hT[(v << 5) + i], acc);
        s_r1[tid] = acc;
    }
    __syncthreads();

    // out = (r @ Wrp + brp) @ Wout + bout
    if (tid < H_) {
        float acc = brp[tid];
        #pragma unroll 16
        for (int k = 0; k < 2 * HALF_; ++k) acc = fmaf(s_r1[k], Wrp[k * H_ + tid], acc);
        s_tmp[tid] = acc;
    }
    __syncthreads();
    if (tid < V_) {
        float acc = bout[tid];
        #pragma unroll 16
        for (int d = 0; d < H_; ++d) acc = fmaf(s_tmp[d], Wout[d * V_ + tid], acc);
        out[b * V_ + tid] = acc;
    }
}

// ---------------------------------------------------------------------------
extern "C" void kernel_launch(void* const* d_in, const int* in_sizes, int n_in,
                              void* d_out, int out_size)
{
    const int*   seq   = (const int*)d_in[0];
    const float* embed = (const float*)d_in[1];
    const float* W1    = (const float*)d_in[2];
    const float* b1    = (const float*)d_in[3];
    const float* W2    = (const float*)d_in[4];
    const float* b2    = (const float*)d_in[5];
    const float* gamma = (const float*)d_in[6];
    const float* beta  = (const float*)d_in[7];
    const float* Ws    = (const float*)d_in[8];
    const float* bs    = (const float*)d_in[9];
    const float* We    = (const float*)d_in[10];
    const float* be    = (const float*)d_in[11];
    const float* Wrp   = (const float*)d_in[12];
    const float* brp   = (const float*)d_in[13];
    const float* Wout  = (const float*)d_in[14];
    const float* bout  = (const float*)d_in[15];
    float* out = (float*)d_out;

    static int smem_set = 0;
    const int smem_bytes = SMEM_FLOATS * 4 + 64;
    if (!smem_set) {
        cudaFuncSetAttribute(scan_kernel,
                             cudaFuncAttributeMaxDynamicSharedMemorySize, smem_bytes);
        smem_set = 1;
    }

    build_tables<<<V_, 128>>>(embed, W1, b1, W2, b2, gamma, beta, Ws, bs, We, be);
    scan_kernel<<<B_, NT_, smem_bytes>>>(seq, Wrp, brp, Wout, bout, out);
}